// round 7
// baseline (speedup 1.0000x reference)
#include <cuda_runtime.h>
#include <cuda_fp16.h>
#include <cstdint>
#include <math.h>

#define BB   2
#define SS   2048
#define DM   2048
#define HQn  32
#define HKVn 8
#define DHn  64
#define ROWS (BB * SS)          // 4096
#define DKV  (HKVn * DHn)       // 512
#define KDIM 2048

#define SCALE_Q (0.125f * 1.44269504088896340736f)   // 1/sqrt(64) * log2(e)

// ---------------- scratch ----------------
__device__ __half g_WqF[DM * DM];                // transposed fp16 weights [N][K]
__device__ __half g_WkF[DKV * KDIM];
__device__ __half g_WvF[DKV * KDIM];
__device__ __half g_WoF[DM * DM];
__device__ __half g_Ch[ROWS * DM];               // split attention ctx hi
__device__ __half g_Cl[ROWS * DM];               // split attention ctx lo
__device__ __half g_Qh[BB * HQn * SS * DHn];     // [b,hq,s,d] split
__device__ __half g_Ql[BB * HQn * SS * DHn];
__device__ __half g_Kf[BB * HKVn * SS * DHn];    // [b,hk,s,d] single fp16
__device__ __half g_Vf[BB * HKVn * SS * DHn];

// ---------------- helpers ----------------
__device__ __forceinline__ uint32_t smem_u32(const void* p) {
    uint32_t r;
    asm("{ .reg .u64 t; cvta.to.shared.u64 t, %1; cvt.u32.u64 %0, t; }" : "=r"(r) : "l"(p));
    return r;
}
__device__ __forceinline__ uint32_t packh(float x0, float x1) {
    uint32_t r;   // mem order: low half = x0
    asm("cvt.rn.f16x2.f32 %0, %1, %2;" : "=r"(r) : "f"(x1), "f"(x0));
    return r;
}
__device__ __forceinline__ void sts64(uint32_t a, uint32_t x, uint32_t y) {
    asm volatile("st.shared.v2.b32 [%0], {%1,%2};" :: "r"(a), "r"(x), "r"(y));
}
__device__ __forceinline__ void sts128(uint32_t a, uint4 v) {
    asm volatile("st.shared.v4.b32 [%0], {%1,%2,%3,%4};"
                 :: "r"(a), "r"(v.x), "r"(v.y), "r"(v.z), "r"(v.w));
}
__device__ __forceinline__ void ldsm4(uint32_t a, uint32_t r[4]) {
    asm volatile("ldmatrix.sync.aligned.m8n8.x4.shared.b16 {%0,%1,%2,%3}, [%4];"
                 : "=r"(r[0]), "=r"(r[1]), "=r"(r[2]), "=r"(r[3]) : "r"(a));
}
__device__ __forceinline__ void ldsm4t(uint32_t a, uint32_t r[4]) {
    asm volatile("ldmatrix.sync.aligned.m8n8.x4.trans.shared.b16 {%0,%1,%2,%3}, [%4];"
                 : "=r"(r[0]), "=r"(r[1]), "=r"(r[2]), "=r"(r[3]) : "r"(a));
}
__device__ __forceinline__ void mma_f16(float c[4], const uint32_t a[4], const uint32_t b[2]) {
    asm volatile("mma.sync.aligned.m16n8k16.row.col.f32.f16.f16.f32 "
                 "{%0,%1,%2,%3},{%4,%5,%6,%7},{%8,%9},{%0,%1,%2,%3};"
                 : "+f"(c[0]), "+f"(c[1]), "+f"(c[2]), "+f"(c[3])
                 : "r"(a[0]), "r"(a[1]), "r"(a[2]), "r"(a[3]), "r"(b[0]), "r"(b[1]));
}
__device__ __forceinline__ void cp16(uint32_t dst, const void* src) {
    asm volatile("cp.async.cg.shared.global [%0], [%1], 16;" :: "r"(dst), "l"(src));
}
#define CP_COMMIT() asm volatile("cp.async.commit_group;" ::: "memory")
template<int N> __device__ __forceinline__ void cp_wait() {
    asm volatile("cp.async.wait_group %0;" :: "n"(N) : "memory");
}
__device__ __forceinline__ void split_store_h(__half* Ch, __half* Cl,
                                              size_t idx, float x0, float x1) {
    float h0 = __half2float(__float2half(x0));
    float h1 = __half2float(__float2half(x1));
    *(uint32_t*)(Ch + idx) = packh(x0, x1);
    *(uint32_t*)(Cl + idx) = packh(x0 - h0, x1 - h1);
}

// ---------------------------------------------------------------------------
// Weight transpose + fp16 round:  Wf[n][k] = (half) W[k][n]
// ---------------------------------------------------------------------------
__global__ __launch_bounds__(256)
void wconv(const float* __restrict__ W, __half* __restrict__ Wf, int N)
{
    __shared__ float t[32][33];
    int n0 = blockIdx.x * 32, k0 = blockIdx.y * 32;
    int tx = threadIdx.x, ty = threadIdx.y;   // 32 x 8
#pragma unroll
    for (int i = ty; i < 32; i += 8)
        t[i][tx] = W[(size_t)(k0 + i) * N + n0 + tx];
    __syncthreads();
#pragma unroll
    for (int i = ty; i < 32; i += 8)
        Wf[(size_t)(n0 + i) * KDIM + k0 + tx] = __float2half(t[tx][i]);
}

// ---------------------------------------------------------------------------
// HMMA GEMM, 128x128 tile, BK=32, double-buffered smem, 2-term fp16 split
// (A = Ah + Al exact, B single rounded fp16).  2 CTAs/SM.
// AIN  0: A fp32, converted inline.  1: A pre-split fp16 pair (Ahg, Alg).
// OUTK 0: fp32 C row-major.
//      1: split fp16 hi/lo, scaled, head-major [b, head, s, d] (NH heads).
//      2: single fp16, head-major.
// ---------------------------------------------------------------------------
#define ST_SZ   30720
#define AH_OFF  0
#define AL_OFF  10240
#define B_OFF   20480
#define GEMM_SMEM (2 * ST_SZ)   // 61440

template<int AIN, int OUTK, int NH>
__global__ __launch_bounds__(256, 2)
void gemm_hmma(const float* __restrict__ Af,
               const __half* __restrict__ Ahg, const __half* __restrict__ Alg,
               const __half* __restrict__ Bf, float* __restrict__ C,
               __half* __restrict__ Ch, __half* __restrict__ Cl,
               float scale, int N)
{
    extern __shared__ char smem[];
    const uint32_t sb = smem_u32(smem);
    const int tid = threadIdx.x;
    const int wid = tid >> 5, lane = tid & 31;
    const int wm = wid >> 2, wn = wid & 3;
    const int m0 = blockIdx.y * 128, n0 = blockIdx.x * 128;

    // global-load mappings
    const int arow = tid >> 3, acol = (tid & 7) * 4;   // fp32 A: 4 rows stride 32
    const int hrow = tid >> 2, hcol = (tid & 3) * 8;   // fp16 rows: 2 rows stride 64

    const float* Afb = Af + (size_t)(m0 + arow) * KDIM + acol;
    const __half* Ahb = Ahg + (size_t)(m0 + hrow) * KDIM + hcol;
    const __half* Alb = Alg + (size_t)(m0 + hrow) * KDIM + hcol;
    const __half* Bfb = Bf + (size_t)(n0 + hrow) * KDIM + hcol;

    const uint32_t aRow = (uint32_t)(wm * 64 + (lane & 15)) * 80 + (lane >> 4) * 16;
    const uint32_t bRow = (uint32_t)(wn * 32 + (lane & 7) + (lane >> 4) * 8) * 80
                        + ((lane >> 3) & 1) * 16;

    float acc[4][4][4];
#pragma unroll
    for (int i = 0; i < 4; i++)
#pragma unroll
        for (int j = 0; j < 4; j++)
#pragma unroll
            for (int r = 0; r < 4; r++) acc[i][j][r] = 0.0f;

    float4 fa[4];
    uint4  fah[2], fal[2], fb[2];

    auto fetch = [&](int kc) {
        if (AIN == 0) {
#pragma unroll
            for (int p = 0; p < 4; p++)
                fa[p] = *(const float4*)(Afb + (size_t)(p * 32) * KDIM + kc);
        } else {
#pragma unroll
            for (int p = 0; p < 2; p++) {
                fah[p] = *(const uint4*)(Ahb + (size_t)(p * 64) * KDIM + kc);
                fal[p] = *(const uint4*)(Alb + (size_t)(p * 64) * KDIM + kc);
            }
        }
#pragma unroll
        for (int p = 0; p < 2; p++)
            fb[p] = *(const uint4*)(Bfb + (size_t)(p * 64) * KDIM + kc);
    };

    auto store_stage = [&](uint32_t st) {
        if (AIN == 0) {
#pragma unroll
            for (int p = 0; p < 4; p++) {
                uint32_t ad = st + (uint32_t)(arow + p * 32) * 80 + acol * 2;
                float x0 = fa[p].x, x1 = fa[p].y, x2 = fa[p].z, x3 = fa[p].w;
                float h0 = __half2float(__float2half(x0));
                float h1 = __half2float(__float2half(x1));
                float h2 = __half2float(__float2half(x2));
                float h3 = __half2float(__float2half(x3));
                sts64(ad + AH_OFF, packh(x0, x1), packh(x2, x3));
                sts64(ad + AL_OFF, packh(x0 - h0, x1 - h1), packh(x2 - h2, x3 - h3));
            }
        } else {
#pragma unroll
            for (int p = 0; p < 2; p++) {
                uint32_t ad = st + (uint32_t)(hrow + p * 64) * 80 + hcol * 2;
                sts128(ad + AH_OFF, fah[p]);
                sts128(ad + AL_OFF, fal[p]);
            }
        }
#pragma unroll
        for (int p = 0; p < 2; p++) {
            uint32_t bd = st + (uint32_t)(hrow + p * 64) * 80 + hcol * 2;
            sts128(bd + B_OFF, fb[p]);
        }
    };

    fetch(0);
    store_stage(sb);
    __syncthreads();

    const int NIT = KDIM / 32;
    for (int c = 0; c < NIT; c++) {
        const uint32_t st = sb + (uint32_t)(c & 1) * ST_SZ;

        if (c + 1 < NIT) fetch((c + 1) * 32);

#pragma unroll
        for (int ks = 0; ks < 2; ks++) {
            const uint32_t ko = ks * 32;
            uint32_t ah[4][4], bh[4][2], tmpv[4];
#pragma unroll
            for (int mi = 0; mi < 4; mi++)
                ldsm4(st + AH_OFF + aRow + mi * 1280 + ko, ah[mi]);
#pragma unroll
            for (int j = 0; j < 2; j++) {
                ldsm4(st + B_OFF + bRow + j * 1280 + ko, tmpv);
                bh[2*j][0] = tmpv[0]; bh[2*j][1] = tmpv[1];
                bh[2*j+1][0] = tmpv[2]; bh[2*j+1][1] = tmpv[3];
            }
#pragma unroll
            for (int mi = 0; mi < 4; mi++)
#pragma unroll
                for (int nj = 0; nj < 4; nj++)
                    mma_f16(acc[mi][nj], ah[mi], bh[nj]);

            uint32_t al[4][4];
#pragma unroll
            for (int mi = 0; mi < 4; mi++)
                ldsm4(st + AL_OFF + aRow + mi * 1280 + ko, al[mi]);
#pragma unroll
            for (int mi = 0; mi < 4; mi++)
#pragma unroll
                for (int nj = 0; nj < 4; nj++)
                    mma_f16(acc[mi][nj], al[mi], bh[nj]);
        }

        if (c + 1 < NIT) store_stage(sb + (uint32_t)((c + 1) & 1) * ST_SZ);
        __syncthreads();
    }

    const int rbase = m0 + wm * 64 + (lane >> 2);
    const int cbase = n0 + wn * 32 + (lane & 3) * 2;
#pragma unroll
    for (int mi = 0; mi < 4; mi++)
#pragma unroll
        for (int nj = 0; nj < 4; nj++) {
            int r0 = rbase + mi * 16;
            int cc = cbase + nj * 8;
            if (OUTK == 0) {
                *(float2*)(C + (size_t)r0 * N + cc)       = make_float2(acc[mi][nj][0], acc[mi][nj][1]);
                *(float2*)(C + (size_t)(r0 + 8) * N + cc) = make_float2(acc[mi][nj][2], acc[mi][nj][3]);
            } else {
                int bb0 = r0 >> 11, ss0 = r0 & 2047;
                int hh = cc >> 6, dd = cc & 63;
                size_t i0 = (((size_t)(bb0 * NH + hh)) * SS + ss0) * 64 + dd;
                int r1 = r0 + 8;
                int bb1 = r1 >> 11, ss1 = r1 & 2047;
                size_t i1 = (((size_t)(bb1 * NH + hh)) * SS + ss1) * 64 + dd;
                if (OUTK == 1) {
                    split_store_h(Ch, Cl, i0, acc[mi][nj][0] * scale, acc[mi][nj][1] * scale);
                    split_store_h(Ch, Cl, i1, acc[mi][nj][2] * scale, acc[mi][nj][3] * scale);
                } else {
                    *(uint32_t*)(Ch + i0) = packh(acc[mi][nj][0], acc[mi][nj][1]);
                    *(uint32_t*)(Ch + i1) = packh(acc[mi][nj][2], acc[mi][nj][3]);
                }
            }
        }
}

// ---------------------------------------------------------------------------
// HMMA flash attention, fp16 2-term split (Q split / K single, P split / V single)
// ---------------------------------------------------------------------------
#define AT_STRIDE 144
#define KF_OFF 0
#define VF_OFF 9216
#define AT_STAGE 18432
#define ATT_SMEM (2 * AT_STAGE)   // 36864

__global__ __launch_bounds__(256, 1)
void attn_mma(const __half* __restrict__ Qh_, const __half* __restrict__ Ql_,
              const __half* __restrict__ Kf_, const __half* __restrict__ Vf_,
              __half* __restrict__ Ch, __half* __restrict__ Cl)
{
    extern __shared__ char smem[];
    const uint32_t sb = smem_u32(smem);
    const int tid = threadIdx.x, wid = tid >> 5, lane = tid & 31;
    const int bh = blockIdx.y;
    const int b = bh >> 5, hq = bh & 31, hk = hq >> 2;
    const int q0 = blockIdx.x * 128;

    const __half* Qhb = Qh_ + ((size_t)bh * SS + q0) * 64;
    const __half* Qlb = Ql_ + ((size_t)bh * SS + q0) * 64;
    const size_t kvoff = (size_t)(b * HKVn + hk) * SS * 64;
    const __half* Kfb = Kf_ + kvoff;
    const __half* Vfb = Vf_ + kvoff;

    // stage Q (hi at 0, lo at 18432), extract frags, then reuse smem for K/V
    for (int i = tid; i < 1024; i += 256) {
        int r = i >> 3, ch = i & 7;
        *(uint4*)(smem + r * AT_STRIDE + ch * 16)         = *(const uint4*)(Qhb + (size_t)r * 64 + ch * 8);
        *(uint4*)(smem + 18432 + r * AT_STRIDE + ch * 16) = *(const uint4*)(Qlb + (size_t)r * 64 + ch * 8);
    }
    __syncthreads();

    uint32_t qh[4][4], ql[4][4];
    {
        uint32_t aAddr = sb + (uint32_t)(wid * 16 + (lane & 15)) * AT_STRIDE + (lane >> 4) * 16;
#pragma unroll
        for (int kc = 0; kc < 4; kc++) {
            ldsm4(aAddr + kc * 32, qh[kc]);
            ldsm4(aAddr + 18432 + kc * 32, ql[kc]);
        }
    }
    __syncthreads();

    auto load_tile = [&](int kt, uint32_t st) {
        size_t base = (size_t)kt * 64 * 64;
#pragma unroll
        for (int i = tid; i < 512; i += 256) {
            int r = i >> 3, ch = i & 7;
            uint32_t d = st + r * AT_STRIDE + ch * 16;
            size_t s = base + (size_t)r * 64 + ch * 8;
            cp16(d + KF_OFF, Kfb + s);
            cp16(d + VF_OFF, Vfb + s);
        }
    };

    float m0 = -1e30f, m1 = -1e30f, l0 = 0.0f, l1 = 0.0f;
    float ctx[8][4];
#pragma unroll
    for (int j = 0; j < 8; j++)
#pragma unroll
        for (int e = 0; e < 4; e++) ctx[j][e] = 0.0f;

    load_tile(0, sb);
    CP_COMMIT();

    const int NKT = SS / 64;
    for (int kt = 0; kt < NKT; kt++) {
        const uint32_t st = sb + (uint32_t)(kt & 1) * AT_STAGE;
        if (kt + 1 < NKT) {
            load_tile(kt + 1, sb + (uint32_t)((kt + 1) & 1) * AT_STAGE);
            CP_COMMIT();
            cp_wait<1>();
        } else {
            cp_wait<0>();
        }
        __syncthreads();

        // ---- S = Q @ K^T (2-term split), log2 units ----
        float sS[8][4];
#pragma unroll
        for (int j = 0; j < 8; j++)
#pragma unroll
            for (int e = 0; e < 4; e++) sS[j][e] = 0.0f;

        const uint32_t kAddr = st + KF_OFF + (uint32_t)((lane >> 4) * 8 + (lane & 7)) * AT_STRIDE
                             + ((lane >> 3) & 1) * 16;
#pragma unroll
        for (int kc = 0; kc < 4; kc++) {
            uint32_t bK[8][2], t[4];
#pragma unroll
            for (int np = 0; np < 4; np++) {
                ldsm4(kAddr + np * 2304 + kc * 32, t);
                bK[2*np][0] = t[0]; bK[2*np][1] = t[1];
                bK[2*np+1][0] = t[2]; bK[2*np+1][1] = t[3];
            }
#pragma unroll
            for (int nj = 0; nj < 8; nj++) mma_f16(sS[nj], qh[kc], bK[nj]);
#pragma unroll
            for (int nj = 0; nj < 8; nj++) mma_f16(sS[nj], ql[kc], bK[nj]);
        }

        // ---- online softmax (base 2) ----
        float mx0 = -1e30f, mx1 = -1e30f;
#pragma unroll
        for (int j = 0; j < 8; j++) {
            mx0 = fmaxf(mx0, fmaxf(sS[j][0], sS[j][1]));
            mx1 = fmaxf(mx1, fmaxf(sS[j][2], sS[j][3]));
        }
        mx0 = fmaxf(mx0, __shfl_xor_sync(0xffffffffu, mx0, 1));
        mx0 = fmaxf(mx0, __shfl_xor_sync(0xffffffffu, mx0, 2));
        mx1 = fmaxf(mx1, __shfl_xor_sync(0xffffffffu, mx1, 1));
        mx1 = fmaxf(mx1, __shfl_xor_sync(0xffffffffu, mx1, 2));

        float mn0 = fmaxf(m0, mx0), mn1 = fmaxf(m1, mx1);
        float al0 = exp2f(m0 - mn0), al1 = exp2f(m1 - mn1);
        m0 = mn0; m1 = mn1;

        float rs0 = 0.0f, rs1 = 0.0f;
#pragma unroll
        for (int j = 0; j < 8; j++) {
            sS[j][0] = exp2f(sS[j][0] - mn0);
            sS[j][1] = exp2f(sS[j][1] - mn0);
            sS[j][2] = exp2f(sS[j][2] - mn1);
            sS[j][3] = exp2f(sS[j][3] - mn1);
            rs0 += sS[j][0] + sS[j][1];
            rs1 += sS[j][2] + sS[j][3];
        }
        rs0 += __shfl_xor_sync(0xffffffffu, rs0, 1);
        rs0 += __shfl_xor_sync(0xffffffffu, rs0, 2);
        rs1 += __shfl_xor_sync(0xffffffffu, rs1, 1);
        rs1 += __shfl_xor_sync(0xffffffffu, rs1, 2);
        l0 = l0 * al0 + rs0;
        l1 = l1 * al1 + rs1;

#pragma unroll
        for (int j = 0; j < 8; j++) {
            ctx[j][0] *= al0; ctx[j][1] *= al0;
            ctx[j][2] *= al1; ctx[j][3] *= al1;
        }

        // ---- ctx += P @ V (P split, V single) ----
        const uint32_t vAddr = st + VF_OFF + (uint32_t)(lane & 15) * AT_STRIDE + (lane >> 4) * 16;
#pragma unroll
        for (int kc = 0; kc < 4; kc++) {
            float x0 = sS[2*kc][0],   x1 = sS[2*kc][1],   x2 = sS[2*kc][2],   x3 = sS[2*kc][3];
            float y0 = sS[2*kc+1][0], y1 = sS[2*kc+1][1], y2 = sS[2*kc+1][2], y3 = sS[2*kc+1][3];
            uint32_t aPh[4], aPl[4];
            aPh[0] = packh(x0, x1); aPh[1] = packh(x2, x3);
            aPh[2] = packh(y0, y1); aPh[3] = packh(y2, y3);
            float hx0 = __half2float(__float2half(x0));
            float hx1 = __half2float(__float2half(x1));
            float hx2 = __half2float(__float2half(x2));
            float hx3 = __half2float(__float2half(x3));
            float hy0 = __half2float(__float2half(y0));
            float hy1 = __half2float(__float2half(y1));
            float hy2 = __half2float(__float2half(y2));
            float hy3 = __half2float(__float2half(y3));
            aPl[0] = packh(x0 - hx0, x1 - hx1); aPl[1] = packh(x2 - hx2, x3 - hx3);
            aPl[2] = packh(y0 - hy0, y1 - hy1); aPl[3] = packh(y2 - hy2, y3 - hy3);

#pragma unroll
            for (int dp = 0; dp < 4; dp++) {
                uint32_t t[4];
                ldsm4t(vAddr + kc * 2304 + dp * 32, t);
                uint32_t b0[2] = { t[0], t[1] }, b1[2] = { t[2], t[3] };
                mma_f16(ctx[2*dp],   aPh, b0);
                mma_f16(ctx[2*dp+1], aPh, b1);
                mma_f16(ctx[2*dp],   aPl, b0);
                mma_f16(ctx[2*dp+1], aPl, b1);
            }
        }
        __syncthreads();
    }

    // ---- epilogue: normalize, write split fp16 ctx [b, s, hq*64+d] ----
    float inv0 = 1.0f / l0, inv1 = 1.0f / l1;
    int r0 = q0 + wid * 16 + (lane >> 2);
    size_t obase = (size_t)b * SS * DM + (size_t)hq * 64;
#pragma unroll
    for (int nj = 0; nj < 8; nj++) {
        int cc = nj * 8 + (lane & 3) * 2;
        split_store_h(Ch, Cl, obase + (size_t)r0 * DM + cc,
                      ctx[nj][0] * inv0, ctx[nj][1] * inv0);
        split_store_h(Ch, Cl, obase + (size_t)(r0 + 8) * DM + cc,
                      ctx[nj][2] * inv1, ctx[nj][3] * inv1);
    }
}

// ---------------------------------------------------------------------------
extern "C" void kernel_launch(void* const* d_in, const int* in_sizes, int n_in,
                              void* d_out, int out_size)
{
    const float* q  = (const float*)d_in[0];
    const float* k  = (const float*)d_in[1];
    const float* v  = (const float*)d_in[2];
    const float* Wq = (const float*)d_in[3];
    const float* Wk = (const float*)d_in[4];
    const float* Wv = (const float*)d_in[5];
    const float* Wo = (const float*)d_in[6];
    float* out = (float*)d_out;

    __half *WqF, *WkF, *WvF, *WoF, *Ch, *Cl, *Qh, *Ql, *Kf, *Vf;
    cudaGetSymbolAddress((void**)&WqF, g_WqF);
    cudaGetSymbolAddress((void**)&WkF, g_WkF);
    cudaGetSymbolAddress((void**)&WvF, g_WvF);
    cudaGetSymbolAddress((void**)&WoF, g_WoF);
    cudaGetSymbolAddress((void**)&Ch, g_Ch);
    cudaGetSymbolAddress((void**)&Cl, g_Cl);
    cudaGetSymbolAddress((void**)&Qh, g_Qh);
    cudaGetSymbolAddress((void**)&Ql, g_Ql);
    cudaGetSymbolAddress((void**)&Kf, g_Kf);
    cudaGetSymbolAddress((void**)&Vf, g_Vf);

    cudaFuncSetAttribute((const void*)&gemm_hmma<0,1,32>, cudaFuncAttributeMaxDynamicSharedMemorySize, GEMM_SMEM);
    cudaFuncSetAttribute((const void*)&gemm_hmma<0,2,8>,  cudaFuncAttributeMaxDynamicSharedMemorySize, GEMM_SMEM);
    cudaFuncSetAttribute((const void*)&gemm_hmma<1,0,0>,  cudaFuncAttributeMaxDynamicSharedMemorySize, GEMM_SMEM);
    cudaFuncSetAttribute((const void*)&attn_mma,          cudaFuncAttributeMaxDynamicSharedMemorySize, ATT_SMEM);

    dim3 wblk(32, 8);

    // all weight converts upfront (independent buffers)
    wconv<<<dim3(DM / 32, KDIM / 32), wblk>>>(Wq, WqF, DM);
    wconv<<<dim3(DKV / 32, KDIM / 32), wblk>>>(Wk, WkF, DKV);
    wconv<<<dim3(DKV / 32, KDIM / 32), wblk>>>(Wv, WvF, DKV);
    wconv<<<dim3(DM / 32, KDIM / 32), wblk>>>(Wo, WoF, DM);

    // projections
    gemm_hmma<0,1,32><<<dim3(DM / 128, ROWS / 128), 256, GEMM_SMEM>>>(
        q, nullptr, nullptr, WqF, nullptr, Qh, Ql, SCALE_Q, DM);
    gemm_hmma<0,2,8><<<dim3(DKV / 128, ROWS / 128), 256, GEMM_SMEM>>>(
        k, nullptr, nullptr, WkF, nullptr, Kf, nullptr, 1.0f, DKV);
    gemm_hmma<0,2,8><<<dim3(DKV / 128, ROWS / 128), 256, GEMM_SMEM>>>(
        v, nullptr, nullptr, WvF, nullptr, Vf, nullptr, 1.0f, DKV);

    // attention (writes split fp16 ctx)
    attn_mma<<<dim3(SS / 128, BB * HQn), 256, ATT_SMEM>>>(Qh, Ql, Kf, Vf, Ch, Cl);

    // output projection (split fp16 A in, fp32 out)
    gemm_hmma<1,0,0><<<dim3(DM / 128, ROWS / 128), 256, GEMM_SMEM>>>(
        nullptr, Ch, Cl, WoF, out, nullptr, nullptr, 1.0f, DM);
}

// round 8
// speedup vs baseline: 1.0354x; 1.0354x over previous
#include <cuda_runtime.h>
#include <cuda_fp16.h>
#include <cstdint>
#include <math.h>

#define BB   2
#define SS   2048
#define DM   2048
#define HQn  32
#define HKVn 8
#define DHn  64
#define ROWS (BB * SS)          // 4096
#define DKV  (HKVn * DHn)       // 512
#define KDIM 2048

#define SCALE_Q (0.125f * 1.44269504088896340736f)   // 1/sqrt(64) * log2(e)

// ---------------- scratch ----------------
__device__ __half g_WqF[DM * DM];                 // transposed fp16 weights [N][K]
__device__ __half g_WkF[DKV * KDIM];
__device__ __half g_WvF[DKV * KDIM];
__device__ __half g_WoF[DM * DM];
__device__ __half g_Ch[ROWS * DM];                // split attention ctx hi
__device__ __half g_Cl[ROWS * DM];                // split attention ctx lo
__device__ __half g_Qh[BB * HQn * SS * DHn];      // [b,hq,s,d] split
__device__ __half g_Ql[BB * HQn * SS * DHn];
__device__ __half g_Kf[BB * HKVn * SS * DHn];     // [b,hk,s,d] single fp16
__device__ __half g_Vf[BB * HKVn * SS * DHn];

// ---------------- helpers ----------------
__device__ __forceinline__ uint32_t smem_u32(const void* p) {
    uint32_t r;
    asm("{ .reg .u64 t; cvta.to.shared.u64 t, %1; cvt.u32.u64 %0, t; }" : "=r"(r) : "l"(p));
    return r;
}
__device__ __forceinline__ uint32_t packh(float x0, float x1) {
    uint32_t r;   // mem order: low half = x0
    asm("cvt.rn.f16x2.f32 %0, %1, %2;" : "=r"(r) : "f"(x1), "f"(x0));
    return r;
}
__device__ __forceinline__ void sts64(uint32_t a, uint32_t x, uint32_t y) {
    asm volatile("st.shared.v2.b32 [%0], {%1,%2};" :: "r"(a), "r"(x), "r"(y));
}
__device__ __forceinline__ void sts128(uint32_t a, uint4 v) {
    asm volatile("st.shared.v4.b32 [%0], {%1,%2,%3,%4};"
                 :: "r"(a), "r"(v.x), "r"(v.y), "r"(v.z), "r"(v.w));
}
__device__ __forceinline__ void ldsm4(uint32_t a, uint32_t r[4]) {
    asm volatile("ldmatrix.sync.aligned.m8n8.x4.shared.b16 {%0,%1,%2,%3}, [%4];"
                 : "=r"(r[0]), "=r"(r[1]), "=r"(r[2]), "=r"(r[3]) : "r"(a));
}
__device__ __forceinline__ void ldsm4t(uint32_t a, uint32_t r[4]) {
    asm volatile("ldmatrix.sync.aligned.m8n8.x4.trans.shared.b16 {%0,%1,%2,%3}, [%4];"
                 : "=r"(r[0]), "=r"(r[1]), "=r"(r[2]), "=r"(r[3]) : "r"(a));
}
__device__ __forceinline__ void mma_f16(float c[4], const uint32_t a[4], const uint32_t b[2]) {
    asm volatile("mma.sync.aligned.m16n8k16.row.col.f32.f16.f16.f32 "
                 "{%0,%1,%2,%3},{%4,%5,%6,%7},{%8,%9},{%0,%1,%2,%3};"
                 : "+f"(c[0]), "+f"(c[1]), "+f"(c[2]), "+f"(c[3])
                 : "r"(a[0]), "r"(a[1]), "r"(a[2]), "r"(a[3]), "r"(b[0]), "r"(b[1]));
}
__device__ __forceinline__ void cp16(uint32_t dst, const void* src) {
    asm volatile("cp.async.cg.shared.global [%0], [%1], 16;" :: "r"(dst), "l"(src));
}
#define CP_COMMIT() asm volatile("cp.async.commit_group;" ::: "memory")
template<int N> __device__ __forceinline__ void cp_wait() {
    asm volatile("cp.async.wait_group %0;" :: "n"(N) : "memory");
}
__device__ __forceinline__ void split_store_h(__half* Ch, __half* Cl,
                                              size_t idx, float x0, float x1) {
    float h0 = __half2float(__float2half(x0));
    float h1 = __half2float(__float2half(x1));
    *(uint32_t*)(Ch + idx) = packh(x0, x1);
    *(uint32_t*)(Cl + idx) = packh(x0 - h0, x1 - h1);
}

// ---------------------------------------------------------------------------
// Weight transpose + fp16 round:  Wf[n][k] = (half) W[k][n]
// ---------------------------------------------------------------------------
__global__ __launch_bounds__(256)
void wconv(const float* __restrict__ W, __half* __restrict__ Wf, int N)
{
    __shared__ float t[32][33];
    int n0 = blockIdx.x * 32, k0 = blockIdx.y * 32;
    int tx = threadIdx.x, ty = threadIdx.y;   // 32 x 8
#pragma unroll
    for (int i = ty; i < 32; i += 8)
        t[i][tx] = W[(size_t)(k0 + i) * N + n0 + tx];
    __syncthreads();
#pragma unroll
    for (int i = ty; i < 32; i += 8)
        Wf[(size_t)(n0 + i) * KDIM + k0 + tx] = __float2half(t[tx][i]);
}

// ---------------------------------------------------------------------------
// HMMA GEMM, CTA tile 128xBN (BN=256 or 128), warp tile 64x(BN/4), 8 warps 2x4,
// BK=32, double-buffered smem, 2-term fp16 split (A = Ah + Al, B single fp16).
// AIN  0: A fp32, converted inline.  1: A pre-split fp16 pair (Ahg, Alg).
// OUTK 0: fp32 C row-major.
//      1: split fp16 hi/lo, scaled, head-major [b, head, s, d] (NH heads of 64).
//      2: single fp16, head-major.
// ---------------------------------------------------------------------------
#define AH_OFF  0
#define AL_OFF  10240

template<int AIN, int OUTK, int NH, int BN>
__global__ __launch_bounds__(256, 1)
void gemm_hmma(const float* __restrict__ Af,
               const __half* __restrict__ Ahg, const __half* __restrict__ Alg,
               const __half* __restrict__ Bf, float* __restrict__ C,
               __half* __restrict__ Ch, __half* __restrict__ Cl,
               float scale, int N)
{
    constexpr int WN  = BN / 4;           // warp n-tile (64 or 32)
    constexpr int NJ  = WN / 8;           // n8 frags per warp (8 or 4)
    constexpr int NB  = WN / 16;          // B ldsm.x4 per warp per ks (4 or 2)
    constexpr int BP  = BN / 64;          // B gmem loads per thread (4 or 2)
    constexpr int ST  = 20480 + BN * 80;  // stage size
    const int B_OFF = 20480;

    extern __shared__ char smem[];
    const uint32_t sb = smem_u32(smem);
    const int tid = threadIdx.x;
    const int wid = tid >> 5, lane = tid & 31;
    const int wm = wid >> 2, wn = wid & 3;
    const int m0 = blockIdx.y * 128, n0 = blockIdx.x * BN;

    const int arow = tid >> 3, acol = (tid & 7) * 4;
    const int hrow = tid >> 2, hcol = (tid & 3) * 8;

    const float* Afb = Af + (size_t)(m0 + arow) * KDIM + acol;
    const __half* Ahb = Ahg + (size_t)(m0 + hrow) * KDIM + hcol;
    const __half* Alb = Alg + (size_t)(m0 + hrow) * KDIM + hcol;
    const __half* Bfb = Bf + (size_t)(n0 + hrow) * KDIM + hcol;

    const uint32_t aRow = (uint32_t)(wm * 64 + (lane & 15)) * 80 + (lane >> 4) * 16;
    const uint32_t bRow = (uint32_t)(wn * WN + (lane & 7) + (lane >> 4) * 8) * 80
                        + ((lane >> 3) & 1) * 16;

    float acc[4][NJ][4];
#pragma unroll
    for (int i = 0; i < 4; i++)
#pragma unroll
        for (int j = 0; j < NJ; j++)
#pragma unroll
            for (int r = 0; r < 4; r++) acc[i][j][r] = 0.0f;

    float4 fa[4];
    uint4  fah[2], fal[2], fb[BP];

    auto fetch = [&](int kc) {
        if (AIN == 0) {
#pragma unroll
            for (int p = 0; p < 4; p++)
                fa[p] = *(const float4*)(Afb + (size_t)(p * 32) * KDIM + kc);
        } else {
#pragma unroll
            for (int p = 0; p < 2; p++) {
                fah[p] = *(const uint4*)(Ahb + (size_t)(p * 64) * KDIM + kc);
                fal[p] = *(const uint4*)(Alb + (size_t)(p * 64) * KDIM + kc);
            }
        }
#pragma unroll
        for (int p = 0; p < BP; p++)
            fb[p] = *(const uint4*)(Bfb + (size_t)(p * 64) * KDIM + kc);
    };

    auto store_stage = [&](uint32_t st) {
        if (AIN == 0) {
#pragma unroll
            for (int p = 0; p < 4; p++) {
                uint32_t ad = st + (uint32_t)(arow + p * 32) * 80 + acol * 2;
                float x0 = fa[p].x, x1 = fa[p].y, x2 = fa[p].z, x3 = fa[p].w;
                float h0 = __half2float(__float2half(x0));
                float h1 = __half2float(__float2half(x1));
                float h2 = __half2float(__float2half(x2));
                float h3 = __half2float(__float2half(x3));
                sts64(ad + AH_OFF, packh(x0, x1), packh(x2, x3));
                sts64(ad + AL_OFF, packh(x0 - h0, x1 - h1), packh(x2 - h2, x3 - h3));
            }
        } else {
#pragma unroll
            for (int p = 0; p < 2; p++) {
                uint32_t ad = st + (uint32_t)(hrow + p * 64) * 80 + hcol * 2;
                sts128(ad + AH_OFF, fah[p]);
                sts128(ad + AL_OFF, fal[p]);
            }
        }
#pragma unroll
        for (int p = 0; p < BP; p++) {
            uint32_t bd = st + (uint32_t)(hrow + p * 64) * 80 + hcol * 2;
            sts128(bd + B_OFF, fb[p]);
        }
    };

    fetch(0);
    store_stage(sb);
    __syncthreads();

    const int NIT = KDIM / 32;
    for (int c = 0; c < NIT; c++) {
        const uint32_t st = sb + (uint32_t)(c & 1) * ST;

        if (c + 1 < NIT) fetch((c + 1) * 32);

#pragma unroll
        for (int ks = 0; ks < 2; ks++) {
            const uint32_t ko = ks * 32;
            uint32_t a4[4][4], bfr[NJ][2], tmpv[4];
#pragma unroll
            for (int j = 0; j < NB; j++) {
                ldsm4(st + B_OFF + bRow + j * 1280 + ko, tmpv);
                bfr[2*j][0] = tmpv[0]; bfr[2*j][1] = tmpv[1];
                bfr[2*j+1][0] = tmpv[2]; bfr[2*j+1][1] = tmpv[3];
            }
#pragma unroll
            for (int mi = 0; mi < 4; mi++)
                ldsm4(st + AH_OFF + aRow + mi * 1280 + ko, a4[mi]);
#pragma unroll
            for (int mi = 0; mi < 4; mi++)
#pragma unroll
                for (int nj = 0; nj < NJ; nj++)
                    mma_f16(acc[mi][nj], a4[mi], bfr[nj]);
#pragma unroll
            for (int mi = 0; mi < 4; mi++)
                ldsm4(st + AL_OFF + aRow + mi * 1280 + ko, a4[mi]);
#pragma unroll
            for (int mi = 0; mi < 4; mi++)
#pragma unroll
                for (int nj = 0; nj < NJ; nj++)
                    mma_f16(acc[mi][nj], a4[mi], bfr[nj]);
        }

        if (c + 1 < NIT) store_stage(sb + (uint32_t)((c + 1) & 1) * ST);
        __syncthreads();
    }

    const int rbase = m0 + wm * 64 + (lane >> 2);
    const int cbase = n0 + wn * WN + (lane & 3) * 2;
#pragma unroll
    for (int mi = 0; mi < 4; mi++)
#pragma unroll
        for (int nj = 0; nj < NJ; nj++) {
            int r0 = rbase + mi * 16;
            int cc = cbase + nj * 8;
            if (OUTK == 0) {
                *(float2*)(C + (size_t)r0 * N + cc)       = make_float2(acc[mi][nj][0], acc[mi][nj][1]);
                *(float2*)(C + (size_t)(r0 + 8) * N + cc) = make_float2(acc[mi][nj][2], acc[mi][nj][3]);
            } else {
                int bb0 = r0 >> 11, ss0 = r0 & 2047;
                int hh = cc >> 6, dd = cc & 63;
                size_t i0 = (((size_t)(bb0 * NH + hh)) * SS + ss0) * 64 + dd;
                int r1 = r0 + 8;
                int bb1 = r1 >> 11, ss1 = r1 & 2047;
                size_t i1 = (((size_t)(bb1 * NH + hh)) * SS + ss1) * 64 + dd;
                if (OUTK == 1) {
                    split_store_h(Ch, Cl, i0, acc[mi][nj][0] * scale, acc[mi][nj][1] * scale);
                    split_store_h(Ch, Cl, i1, acc[mi][nj][2] * scale, acc[mi][nj][3] * scale);
                } else {
                    *(uint32_t*)(Ch + i0) = packh(acc[mi][nj][0], acc[mi][nj][1]);
                    *(uint32_t*)(Ch + i1) = packh(acc[mi][nj][2], acc[mi][nj][3]);
                }
            }
        }
}

#define GEMM_SMEM_256 (2 * (20480 + 256 * 80))   // 81920
#define GEMM_SMEM_128 (2 * (20480 + 128 * 80))   // 61440

// ---------------------------------------------------------------------------
// HMMA flash attention, fp16 2-term split (Q split / K single, P split / V single)
// ---------------------------------------------------------------------------
#define AT_STRIDE 144
#define KF_OFF 0
#define VF_OFF 9216
#define AT_STAGE 18432
#define ATT_SMEM (2 * AT_STAGE)   // 36864

__global__ __launch_bounds__(256, 1)
void attn_mma(const __half* __restrict__ Qh_, const __half* __restrict__ Ql_,
              const __half* __restrict__ Kf_, const __half* __restrict__ Vf_,
              __half* __restrict__ Ch, __half* __restrict__ Cl)
{
    extern __shared__ char smem[];
    const uint32_t sb = smem_u32(smem);
    const int tid = threadIdx.x, wid = tid >> 5, lane = tid & 31;
    const int bh = blockIdx.y;
    const int b = bh >> 5, hq = bh & 31, hk = hq >> 2;
    const int q0 = blockIdx.x * 128;

    const __half* Qhb = Qh_ + ((size_t)bh * SS + q0) * 64;
    const __half* Qlb = Ql_ + ((size_t)bh * SS + q0) * 64;
    const size_t kvoff = (size_t)(b * HKVn + hk) * SS * 64;
    const __half* Kfb = Kf_ + kvoff;
    const __half* Vfb = Vf_ + kvoff;

    for (int i = tid; i < 1024; i += 256) {
        int r = i >> 3, ch = i & 7;
        *(uint4*)(smem + r * AT_STRIDE + ch * 16)         = *(const uint4*)(Qhb + (size_t)r * 64 + ch * 8);
        *(uint4*)(smem + 18432 + r * AT_STRIDE + ch * 16) = *(const uint4*)(Qlb + (size_t)r * 64 + ch * 8);
    }
    __syncthreads();

    uint32_t qh[4][4], ql[4][4];
    {
        uint32_t aAddr = sb + (uint32_t)(wid * 16 + (lane & 15)) * AT_STRIDE + (lane >> 4) * 16;
#pragma unroll
        for (int kc = 0; kc < 4; kc++) {
            ldsm4(aAddr + kc * 32, qh[kc]);
            ldsm4(aAddr + 18432 + kc * 32, ql[kc]);
        }
    }
    __syncthreads();

    auto load_tile = [&](int kt, uint32_t st) {
        size_t base = (size_t)kt * 64 * 64;
#pragma unroll
        for (int i = tid; i < 512; i += 256) {
            int r = i >> 3, ch = i & 7;
            uint32_t d = st + r * AT_STRIDE + ch * 16;
            size_t s = base + (size_t)r * 64 + ch * 8;
            cp16(d + KF_OFF, Kfb + s);
            cp16(d + VF_OFF, Vfb + s);
        }
    };

    float m0 = -1e30f, m1 = -1e30f, l0 = 0.0f, l1 = 0.0f;
    float ctx[8][4];
#pragma unroll
    for (int j = 0; j < 8; j++)
#pragma unroll
        for (int e = 0; e < 4; e++) ctx[j][e] = 0.0f;

    load_tile(0, sb);
    CP_COMMIT();

    const int NKT = SS / 64;
    for (int kt = 0; kt < NKT; kt++) {
        const uint32_t st = sb + (uint32_t)(kt & 1) * AT_STAGE;
        if (kt + 1 < NKT) {
            load_tile(kt + 1, sb + (uint32_t)((kt + 1) & 1) * AT_STAGE);
            CP_COMMIT();
            cp_wait<1>();
        } else {
            cp_wait<0>();
        }
        __syncthreads();

        float sS[8][4];
#pragma unroll
        for (int j = 0; j < 8; j++)
#pragma unroll
            for (int e = 0; e < 4; e++) sS[j][e] = 0.0f;

        const uint32_t kAddr = st + KF_OFF + (uint32_t)((lane >> 4) * 8 + (lane & 7)) * AT_STRIDE
                             + ((lane >> 3) & 1) * 16;
#pragma unroll
        for (int kc = 0; kc < 4; kc++) {
            uint32_t bK[8][2], t[4];
#pragma unroll
            for (int np = 0; np < 4; np++) {
                ldsm4(kAddr + np * 2304 + kc * 32, t);
                bK[2*np][0] = t[0]; bK[2*np][1] = t[1];
                bK[2*np+1][0] = t[2]; bK[2*np+1][1] = t[3];
            }
#pragma unroll
            for (int nj = 0; nj < 8; nj++) mma_f16(sS[nj], qh[kc], bK[nj]);
#pragma unroll
            for (int nj = 0; nj < 8; nj++) mma_f16(sS[nj], ql[kc], bK[nj]);
        }

        float mx0 = -1e30f, mx1 = -1e30f;
#pragma unroll
        for (int j = 0; j < 8; j++) {
            mx0 = fmaxf(mx0, fmaxf(sS[j][0], sS[j][1]));
            mx1 = fmaxf(mx1, fmaxf(sS[j][2], sS[j][3]));
        }
        mx0 = fmaxf(mx0, __shfl_xor_sync(0xffffffffu, mx0, 1));
        mx0 = fmaxf(mx0, __shfl_xor_sync(0xffffffffu, mx0, 2));
        mx1 = fmaxf(mx1, __shfl_xor_sync(0xffffffffu, mx1, 1));
        mx1 = fmaxf(mx1, __shfl_xor_sync(0xffffffffu, mx1, 2));

        float mn0 = fmaxf(m0, mx0), mn1 = fmaxf(m1, mx1);
        float al0 = exp2f(m0 - mn0), al1 = exp2f(m1 - mn1);
        m0 = mn0; m1 = mn1;

        float rs0 = 0.0f, rs1 = 0.0f;
#pragma unroll
        for (int j = 0; j < 8; j++) {
            sS[j][0] = exp2f(sS[j][0] - mn0);
            sS[j][1] = exp2f(sS[j][1] - mn0);
            sS[j][2] = exp2f(sS[j][2] - mn1);
            sS[j][3] = exp2f(sS[j][3] - mn1);
            rs0 += sS[j][0] + sS[j][1];
            rs1 += sS[j][2] + sS[j][3];
        }
        rs0 += __shfl_xor_sync(0xffffffffu, rs0, 1);
        rs0 += __shfl_xor_sync(0xffffffffu, rs0, 2);
        rs1 += __shfl_xor_sync(0xffffffffu, rs1, 1);
        rs1 += __shfl_xor_sync(0xffffffffu, rs1, 2);
        l0 = l0 * al0 + rs0;
        l1 = l1 * al1 + rs1;

#pragma unroll
        for (int j = 0; j < 8; j++) {
            ctx[j][0] *= al0; ctx[j][1] *= al0;
            ctx[j][2] *= al1; ctx[j][3] *= al1;
        }

        const uint32_t vAddr = st + VF_OFF + (uint32_t)(lane & 15) * AT_STRIDE + (lane >> 4) * 16;
#pragma unroll
        for (int kc = 0; kc < 4; kc++) {
            float x0 = sS[2*kc][0],   x1 = sS[2*kc][1],   x2 = sS[2*kc][2],   x3 = sS[2*kc][3];
            float y0 = sS[2*kc+1][0], y1 = sS[2*kc+1][1], y2 = sS[2*kc+1][2], y3 = sS[2*kc+1][3];
            uint32_t aPh[4], aPl[4];
            aPh[0] = packh(x0, x1); aPh[1] = packh(x2, x3);
            aPh[2] = packh(y0, y1); aPh[3] = packh(y2, y3);
            float hx0 = __half2float(__float2half(x0));
            float hx1 = __half2float(__float2half(x1));
            float hx2 = __half2float(__float2half(x2));
            float hx3 = __half2float(__float2half(x3));
            float hy0 = __half2float(__float2half(y0));
            float hy1 = __half2float(__float2half(y1));
            float hy2 = __half2float(__float2half(y2));
            float hy3 = __half2float(__float2half(y3));
            aPl[0] = packh(x0 - hx0, x1 - hx1); aPl[1] = packh(x2 - hx2, x3 - hx3);
            aPl[2] = packh(y0 - hy0, y1 - hy1); aPl[3] = packh(y2 - hy2, y3 - hy3);

#pragma unroll
            for (int dp = 0; dp < 4; dp++) {
                uint32_t t[4];
                ldsm4t(vAddr + kc * 2304 + dp * 32, t);
                uint32_t b0[2] = { t[0], t[1] }, b1[2] = { t[2], t[3] };
                mma_f16(ctx[2*dp],   aPh, b0);
                mma_f16(ctx[2*dp+1], aPh, b1);
                mma_f16(ctx[2*dp],   aPl, b0);
                mma_f16(ctx[2*dp+1], aPl, b1);
            }
        }
        __syncthreads();
    }

    float inv0 = 1.0f / l0, inv1 = 1.0f / l1;
    int r0 = q0 + wid * 16 + (lane >> 2);
    size_t obase = (size_t)b * SS * DM + (size_t)hq * 64;
#pragma unroll
    for (int nj = 0; nj < 8; nj++) {
        int cc = nj * 8 + (lane & 3) * 2;
        split_store_h(Ch, Cl, obase + (size_t)r0 * DM + cc,
                      ctx[nj][0] * inv0, ctx[nj][1] * inv0);
        split_store_h(Ch, Cl, obase + (size_t)(r0 + 8) * DM + cc,
                      ctx[nj][2] * inv1, ctx[nj][3] * inv1);
    }
}

// ---------------------------------------------------------------------------
extern "C" void kernel_launch(void* const* d_in, const int* in_sizes, int n_in,
                              void* d_out, int out_size)
{
    const float* q  = (const float*)d_in[0];
    const float* k  = (const float*)d_in[1];
    const float* v  = (const float*)d_in[2];
    const float* Wq = (const float*)d_in[3];
    const float* Wk = (const float*)d_in[4];
    const float* Wv = (const float*)d_in[5];
    const float* Wo = (const float*)d_in[6];
    float* out = (float*)d_out;

    __half *WqF, *WkF, *WvF, *WoF, *Ch, *Cl, *Qh, *Ql, *Kf, *Vf;
    cudaGetSymbolAddress((void**)&WqF, g_WqF);
    cudaGetSymbolAddress((void**)&WkF, g_WkF);
    cudaGetSymbolAddress((void**)&WvF, g_WvF);
    cudaGetSymbolAddress((void**)&WoF, g_WoF);
    cudaGetSymbolAddress((void**)&Ch, g_Ch);
    cudaGetSymbolAddress((void**)&Cl, g_Cl);
    cudaGetSymbolAddress((void**)&Qh, g_Qh);
    cudaGetSymbolAddress((void**)&Ql, g_Ql);
    cudaGetSymbolAddress((void**)&Kf, g_Kf);
    cudaGetSymbolAddress((void**)&Vf, g_Vf);

    cudaFuncSetAttribute((const void*)&gemm_hmma<0,1,32,256>, cudaFuncAttributeMaxDynamicSharedMemorySize, GEMM_SMEM_256);
    cudaFuncSetAttribute((const void*)&gemm_hmma<0,2,8,128>,  cudaFuncAttributeMaxDynamicSharedMemorySize, GEMM_SMEM_128);
    cudaFuncSetAttribute((const void*)&gemm_hmma<1,0,0,256>,  cudaFuncAttributeMaxDynamicSharedMemorySize, GEMM_SMEM_256);
    cudaFuncSetAttribute((const void*)&attn_mma,              cudaFuncAttributeMaxDynamicSharedMemorySize, ATT_SMEM);

    dim3 wblk(32, 8);

    // weight converts upfront (independent buffers)
    wconv<<<dim3(DM / 32, KDIM / 32), wblk>>>(Wq, WqF, DM);
    wconv<<<dim3(DKV / 32, KDIM / 32), wblk>>>(Wk, WkF, DKV);
    wconv<<<dim3(DKV / 32, KDIM / 32), wblk>>>(Wv, WvF, DKV);
    wconv<<<dim3(DM / 32, KDIM / 32), wblk>>>(Wo, WoF, DM);

    // Q projection: BN=256, grid (8,32)=256 CTAs
    gemm_hmma<0,1,32,256><<<dim3(DM / 256, ROWS / 128), 256, GEMM_SMEM_256>>>(
        q, nullptr, nullptr, WqF, nullptr, Qh, Ql, SCALE_Q, DM);

    // K / V projections: BN=128 keeps grid at 128 CTAs each (N=512 too narrow for BN=256)
    gemm_hmma<0,2,8,128><<<dim3(DKV / 128, ROWS / 128), 256, GEMM_SMEM_128>>>(
        k, nullptr, nullptr, WkF, nullptr, Kf, nullptr, 1.0f, DKV);
    gemm_hmma<0,2,8,128><<<dim3(DKV / 128, ROWS / 128), 256, GEMM_SMEM_128>>>(
        v, nullptr, nullptr, WvF, nullptr, Vf, nullptr, 1.0f, DKV);

    // attention (writes split fp16 ctx)
    attn_mma<<<dim3(SS / 128, BB * HQn), 256, ATT_SMEM>>>(Qh, Ql, Kf, Vf, Ch, Cl);

    // output projection: BN=256, split fp16 A in, fp32 out
    gemm_hmma<1,0,0,256><<<dim3(DM / 256, ROWS / 128), 256, GEMM_SMEM_256>>>(
        nullptr, Ch, Cl, WoF, out, nullptr, nullptr, 1.0f, DM);
}

// round 9
// speedup vs baseline: 1.2719x; 1.2283x over previous
#include <cuda_runtime.h>
#include <cuda_fp16.h>
#include <cstdint>
#include <math.h>

#define BB   2
#define SS   2048
#define DM   2048
#define HQn  32
#define HKVn 8
#define DHn  64
#define ROWS (BB * SS)          // 4096
#define DKV  (HKVn * DHn)       // 512
#define KDIM 2048

#define SCALE_Q (0.125f * 1.44269504088896340736f)   // 1/sqrt(64) * log2(e)

// ---------------- scratch ----------------
__device__ __half g_WqF[DM * DM];                 // transposed fp16 weights [N][K]
__device__ __half g_WkF[DKV * KDIM];
__device__ __half g_WvF[DKV * KDIM];
__device__ __half g_WoF[DM * DM];
__device__ __half g_Ch[ROWS * DM];                // split attention ctx hi
__device__ __half g_Cl[ROWS * DM];                // split attention ctx lo
__device__ __half g_Qf[BB * HQn * SS * DHn];      // [b,hq,s,d] single fp16 (pre-scaled)
__device__ __half g_Kf[BB * HKVn * SS * DHn];     // [b,hk,s,d] single fp16
__device__ __half g_Vf[BB * HKVn * SS * DHn];

// ---------------- helpers ----------------
__device__ __forceinline__ uint32_t smem_u32(const void* p) {
    uint32_t r;
    asm("{ .reg .u64 t; cvta.to.shared.u64 t, %1; cvt.u32.u64 %0, t; }" : "=r"(r) : "l"(p));
    return r;
}
__device__ __forceinline__ uint32_t packh(float x0, float x1) {
    uint32_t r;   // mem order: low half = x0
    asm("cvt.rn.f16x2.f32 %0, %1, %2;" : "=r"(r) : "f"(x1), "f"(x0));
    return r;
}
__device__ __forceinline__ void sts64(uint32_t a, uint32_t x, uint32_t y) {
    asm volatile("st.shared.v2.b32 [%0], {%1,%2};" :: "r"(a), "r"(x), "r"(y));
}
__device__ __forceinline__ void sts128(uint32_t a, uint4 v) {
    asm volatile("st.shared.v4.b32 [%0], {%1,%2,%3,%4};"
                 :: "r"(a), "r"(v.x), "r"(v.y), "r"(v.z), "r"(v.w));
}
__device__ __forceinline__ void ldsm4(uint32_t a, uint32_t r[4]) {
    asm volatile("ldmatrix.sync.aligned.m8n8.x4.shared.b16 {%0,%1,%2,%3}, [%4];"
                 : "=r"(r[0]), "=r"(r[1]), "=r"(r[2]), "=r"(r[3]) : "r"(a));
}
__device__ __forceinline__ void ldsm4t(uint32_t a, uint32_t r[4]) {
    asm volatile("ldmatrix.sync.aligned.m8n8.x4.trans.shared.b16 {%0,%1,%2,%3}, [%4];"
                 : "=r"(r[0]), "=r"(r[1]), "=r"(r[2]), "=r"(r[3]) : "r"(a));
}
__device__ __forceinline__ void mma_f16(float c[4], const uint32_t a[4], const uint32_t b[2]) {
    asm volatile("mma.sync.aligned.m16n8k16.row.col.f32.f16.f16.f32 "
                 "{%0,%1,%2,%3},{%4,%5,%6,%7},{%8,%9},{%0,%1,%2,%3};"
                 : "+f"(c[0]), "+f"(c[1]), "+f"(c[2]), "+f"(c[3])
                 : "r"(a[0]), "r"(a[1]), "r"(a[2]), "r"(a[3]), "r"(b[0]), "r"(b[1]));
}
__device__ __forceinline__ void cp16(uint32_t dst, const void* src) {
    asm volatile("cp.async.cg.shared.global [%0], [%1], 16;" :: "r"(dst), "l"(src));
}
#define CP_COMMIT() asm volatile("cp.async.commit_group;" ::: "memory")
template<int N> __device__ __forceinline__ void cp_wait() {
    asm volatile("cp.async.wait_group %0;" :: "n"(N) : "memory");
}
__device__ __forceinline__ void split_store_h(__half* Ch, __half* Cl,
                                              size_t idx, float x0, float x1) {
    float h0 = __half2float(__float2half(x0));
    float h1 = __half2float(__float2half(x1));
    *(uint32_t*)(Ch + idx) = packh(x0, x1);
    *(uint32_t*)(Cl + idx) = packh(x0 - h0, x1 - h1);
}

// ---------------------------------------------------------------------------
// Weight transpose + fp16 round, two weights per launch (blockIdx.z selects):
// Wf[n][k] = (half) W[k][n]
// ---------------------------------------------------------------------------
__global__ __launch_bounds__(256)
void wconv2(const float* __restrict__ W0, __half* __restrict__ F0,
            const float* __restrict__ W1, __half* __restrict__ F1, int N)
{
    const float* W = blockIdx.z ? W1 : W0;
    __half* Wf = blockIdx.z ? F1 : F0;
    __shared__ float t[32][33];
    int n0 = blockIdx.x * 32, k0 = blockIdx.y * 32;
    int tx = threadIdx.x, ty = threadIdx.y;   // 32 x 8
#pragma unroll
    for (int i = ty; i < 32; i += 8)
        t[i][tx] = W[(size_t)(k0 + i) * N + n0 + tx];
    __syncthreads();
#pragma unroll
    for (int i = ty; i < 32; i += 8)
        Wf[(size_t)(n0 + i) * KDIM + k0 + tx] = __float2half(t[tx][i]);
}

// ---------------------------------------------------------------------------
// HMMA GEMM, CTA tile 128xBN, warp tile 64x(BN/4), 8 warps 2x4, BK=32,
// double-buffered smem, 2-term fp16 split (A = Ah + Al, B single fp16).
// blockIdx.z==1 switches to secondary (Af2, Bf2, Ch2) problem (KV fusion).
// AIN  0: A fp32 inline-converted.  1: A pre-split fp16 pair.
// OUTK 0: fp32 C row-major.
//      2: single fp16 scaled, head-major [b, head, s, d] (NH heads of 64).
// ---------------------------------------------------------------------------
#define AH_OFF  0
#define AL_OFF  10240

template<int AIN, int OUTK, int NH, int BN>
__global__ __launch_bounds__(256, 1)
void gemm_hmma(const float* __restrict__ Af,
               const __half* __restrict__ Ahg, const __half* __restrict__ Alg,
               const __half* __restrict__ Bf, float* __restrict__ C,
               __half* __restrict__ Ch, __half* __restrict__ Cl,
               float scale, int N,
               const float* __restrict__ Af2, const __half* __restrict__ Bf2,
               __half* __restrict__ Ch2)
{
    constexpr int WN  = BN / 4;
    constexpr int NJ  = WN / 8;
    constexpr int NB  = WN / 16;
    constexpr int BP  = BN / 64;
    constexpr int ST  = 20480 + BN * 80;
    const int B_OFF = 20480;

    const float* AfP = (blockIdx.z ? Af2 : Af);
    const __half* BfP = (blockIdx.z ? Bf2 : Bf);
    __half* ChP = (blockIdx.z ? Ch2 : Ch);

    extern __shared__ char smem[];
    const uint32_t sb = smem_u32(smem);
    const int tid = threadIdx.x;
    const int wid = tid >> 5, lane = tid & 31;
    const int wm = wid >> 2, wn = wid & 3;
    const int m0 = blockIdx.y * 128, n0 = blockIdx.x * BN;

    const int arow = tid >> 3, acol = (tid & 7) * 4;
    const int hrow = tid >> 2, hcol = (tid & 3) * 8;

    const float* Afb = AfP + (size_t)(m0 + arow) * KDIM + acol;
    const __half* Ahb = Ahg + (size_t)(m0 + hrow) * KDIM + hcol;
    const __half* Alb = Alg + (size_t)(m0 + hrow) * KDIM + hcol;
    const __half* Bfb = BfP + (size_t)(n0 + hrow) * KDIM + hcol;

    const uint32_t aRow = (uint32_t)(wm * 64 + (lane & 15)) * 80 + (lane >> 4) * 16;
    const uint32_t bRow = (uint32_t)(wn * WN + (lane & 7) + (lane >> 4) * 8) * 80
                        + ((lane >> 3) & 1) * 16;

    float acc[4][NJ][4];
#pragma unroll
    for (int i = 0; i < 4; i++)
#pragma unroll
        for (int j = 0; j < NJ; j++)
#pragma unroll
            for (int r = 0; r < 4; r++) acc[i][j][r] = 0.0f;

    float4 fa[4];
    uint4  fah[2], fal[2], fb[BP];

    auto fetch = [&](int kc) {
        if (AIN == 0) {
#pragma unroll
            for (int p = 0; p < 4; p++)
                fa[p] = *(const float4*)(Afb + (size_t)(p * 32) * KDIM + kc);
        } else {
#pragma unroll
            for (int p = 0; p < 2; p++) {
                fah[p] = *(const uint4*)(Ahb + (size_t)(p * 64) * KDIM + kc);
                fal[p] = *(const uint4*)(Alb + (size_t)(p * 64) * KDIM + kc);
            }
        }
#pragma unroll
        for (int p = 0; p < BP; p++)
            fb[p] = *(const uint4*)(Bfb + (size_t)(p * 64) * KDIM + kc);
    };

    auto store_stage = [&](uint32_t st) {
        if (AIN == 0) {
#pragma unroll
            for (int p = 0; p < 4; p++) {
                uint32_t ad = st + (uint32_t)(arow + p * 32) * 80 + acol * 2;
                float x0 = fa[p].x, x1 = fa[p].y, x2 = fa[p].z, x3 = fa[p].w;
                float h0 = __half2float(__float2half(x0));
                float h1 = __half2float(__float2half(x1));
                float h2 = __half2float(__float2half(x2));
                float h3 = __half2float(__float2half(x3));
                sts64(ad + AH_OFF, packh(x0, x1), packh(x2, x3));
                sts64(ad + AL_OFF, packh(x0 - h0, x1 - h1), packh(x2 - h2, x3 - h3));
            }
        } else {
#pragma unroll
            for (int p = 0; p < 2; p++) {
                uint32_t ad = st + (uint32_t)(hrow + p * 64) * 80 + hcol * 2;
                sts128(ad + AH_OFF, fah[p]);
                sts128(ad + AL_OFF, fal[p]);
            }
        }
#pragma unroll
        for (int p = 0; p < BP; p++) {
            uint32_t bd = st + (uint32_t)(hrow + p * 64) * 80 + hcol * 2;
            sts128(bd + B_OFF, fb[p]);
        }
    };

    fetch(0);
    store_stage(sb);
    __syncthreads();

    const int NIT = KDIM / 32;
    for (int c = 0; c < NIT; c++) {
        const uint32_t st = sb + (uint32_t)(c & 1) * ST;

        if (c + 1 < NIT) fetch((c + 1) * 32);

#pragma unroll
        for (int ks = 0; ks < 2; ks++) {
            const uint32_t ko = ks * 32;
            uint32_t a4[4][4], bfr[NJ][2], tmpv[4];
#pragma unroll
            for (int j = 0; j < NB; j++) {
                ldsm4(st + B_OFF + bRow + j * 1280 + ko, tmpv);
                bfr[2*j][0] = tmpv[0]; bfr[2*j][1] = tmpv[1];
                bfr[2*j+1][0] = tmpv[2]; bfr[2*j+1][1] = tmpv[3];
            }
#pragma unroll
            for (int mi = 0; mi < 4; mi++)
                ldsm4(st + AH_OFF + aRow + mi * 1280 + ko, a4[mi]);
#pragma unroll
            for (int mi = 0; mi < 4; mi++)
#pragma unroll
                for (int nj = 0; nj < NJ; nj++)
                    mma_f16(acc[mi][nj], a4[mi], bfr[nj]);
#pragma unroll
            for (int mi = 0; mi < 4; mi++)
                ldsm4(st + AL_OFF + aRow + mi * 1280 + ko, a4[mi]);
#pragma unroll
            for (int mi = 0; mi < 4; mi++)
#pragma unroll
                for (int nj = 0; nj < NJ; nj++)
                    mma_f16(acc[mi][nj], a4[mi], bfr[nj]);
        }

        if (c + 1 < NIT) store_stage(sb + (uint32_t)((c + 1) & 1) * ST);
        __syncthreads();
    }

    const int rbase = m0 + wm * 64 + (lane >> 2);
    const int cbase = n0 + wn * WN + (lane & 3) * 2;
#pragma unroll
    for (int mi = 0; mi < 4; mi++)
#pragma unroll
        for (int nj = 0; nj < NJ; nj++) {
            int r0 = rbase + mi * 16;
            int cc = cbase + nj * 8;
            if (OUTK == 0) {
                *(float2*)(C + (size_t)r0 * N + cc)       = make_float2(acc[mi][nj][0], acc[mi][nj][1]);
                *(float2*)(C + (size_t)(r0 + 8) * N + cc) = make_float2(acc[mi][nj][2], acc[mi][nj][3]);
            } else {
                int bb0 = r0 >> 11, ss0 = r0 & 2047;
                int hh = cc >> 6, dd = cc & 63;
                size_t i0 = (((size_t)(bb0 * NH + hh)) * SS + ss0) * 64 + dd;
                int r1 = r0 + 8;
                int bb1 = r1 >> 11, ss1 = r1 & 2047;
                size_t i1 = (((size_t)(bb1 * NH + hh)) * SS + ss1) * 64 + dd;
                *(uint32_t*)(ChP + i0) = packh(acc[mi][nj][0] * scale, acc[mi][nj][1] * scale);
                *(uint32_t*)(ChP + i1) = packh(acc[mi][nj][2] * scale, acc[mi][nj][3] * scale);
            }
        }
}

#define GEMM_SMEM_256 (2 * (20480 + 256 * 80))   // 81920
#define GEMM_SMEM_128 (2 * (20480 + 128 * 80))   // 61440

// ---------------------------------------------------------------------------
// HMMA flash attention, single-fp16 QK and PV (no splits in attention).
// 2 CTAs/SM for softmax-bubble overlap.
// ---------------------------------------------------------------------------
#define AT_STRIDE 144
#define KF_OFF 0
#define VF_OFF 9216
#define AT_STAGE 18432
#define ATT_SMEM (2 * AT_STAGE)   // 36864

__global__ __launch_bounds__(256, 2)
void attn_mma(const __half* __restrict__ Qf_, const __half* __restrict__ Kf_,
              const __half* __restrict__ Vf_,
              __half* __restrict__ Ch, __half* __restrict__ Cl)
{
    extern __shared__ char smem[];
    const uint32_t sb = smem_u32(smem);
    const int tid = threadIdx.x, wid = tid >> 5, lane = tid & 31;
    const int bh = blockIdx.y;
    const int b = bh >> 5, hq = bh & 31, hk = hq >> 2;
    const int q0 = blockIdx.x * 128;

    const __half* Qfb = Qf_ + ((size_t)bh * SS + q0) * 64;
    const size_t kvoff = (size_t)(b * HKVn + hk) * SS * 64;
    const __half* Kfb = Kf_ + kvoff;
    const __half* Vfb = Vf_ + kvoff;

    // stage Q (hi only), extract frags, then reuse smem for K/V
    for (int i = tid; i < 1024; i += 256) {
        int r = i >> 3, ch = i & 7;
        *(uint4*)(smem + r * AT_STRIDE + ch * 16) = *(const uint4*)(Qfb + (size_t)r * 64 + ch * 8);
    }
    __syncthreads();

    uint32_t qh[4][4];
    {
        uint32_t aAddr = sb + (uint32_t)(wid * 16 + (lane & 15)) * AT_STRIDE + (lane >> 4) * 16;
#pragma unroll
        for (int kc = 0; kc < 4; kc++)
            ldsm4(aAddr + kc * 32, qh[kc]);
    }
    __syncthreads();

    auto load_tile = [&](int kt, uint32_t st) {
        size_t base = (size_t)kt * 64 * 64;
#pragma unroll
        for (int i = tid; i < 512; i += 256) {
            int r = i >> 3, ch = i & 7;
            uint32_t d = st + r * AT_STRIDE + ch * 16;
            size_t s = base + (size_t)r * 64 + ch * 8;
            cp16(d + KF_OFF, Kfb + s);
            cp16(d + VF_OFF, Vfb + s);
        }
    };

    float m0 = -1e30f, m1 = -1e30f, l0 = 0.0f, l1 = 0.0f;
    float ctx[8][4];
#pragma unroll
    for (int j = 0; j < 8; j++)
#pragma unroll
        for (int e = 0; e < 4; e++) ctx[j][e] = 0.0f;

    load_tile(0, sb);
    CP_COMMIT();

    const int NKT = SS / 64;
    for (int kt = 0; kt < NKT; kt++) {
        const uint32_t st = sb + (uint32_t)(kt & 1) * AT_STAGE;
        if (kt + 1 < NKT) {
            load_tile(kt + 1, sb + (uint32_t)((kt + 1) & 1) * AT_STAGE);
            CP_COMMIT();
            cp_wait<1>();
        } else {
            cp_wait<0>();
        }
        __syncthreads();

        // ---- S = Q @ K^T (single fp16), log2 units ----
        float sS[8][4];
#pragma unroll
        for (int j = 0; j < 8; j++)
#pragma unroll
            for (int e = 0; e < 4; e++) sS[j][e] = 0.0f;

        const uint32_t kAddr = st + KF_OFF + (uint32_t)((lane >> 4) * 8 + (lane & 7)) * AT_STRIDE
                             + ((lane >> 3) & 1) * 16;
#pragma unroll
        for (int kc = 0; kc < 4; kc++) {
            uint32_t bK[8][2], t[4];
#pragma unroll
            for (int np = 0; np < 4; np++) {
                ldsm4(kAddr + np * 2304 + kc * 32, t);
                bK[2*np][0] = t[0]; bK[2*np][1] = t[1];
                bK[2*np+1][0] = t[2]; bK[2*np+1][1] = t[3];
            }
#pragma unroll
            for (int nj = 0; nj < 8; nj++) mma_f16(sS[nj], qh[kc], bK[nj]);
        }

        // ---- online softmax (base 2) ----
        float mx0 = -1e30f, mx1 = -1e30f;
#pragma unroll
        for (int j = 0; j < 8; j++) {
            mx0 = fmaxf(mx0, fmaxf(sS[j][0], sS[j][1]));
            mx1 = fmaxf(mx1, fmaxf(sS[j][2], sS[j][3]));
        }
        mx0 = fmaxf(mx0, __shfl_xor_sync(0xffffffffu, mx0, 1));
        mx0 = fmaxf(mx0, __shfl_xor_sync(0xffffffffu, mx0, 2));
        mx1 = fmaxf(mx1, __shfl_xor_sync(0xffffffffu, mx1, 1));
        mx1 = fmaxf(mx1, __shfl_xor_sync(0xffffffffu, mx1, 2));

        float mn0 = fmaxf(m0, mx0), mn1 = fmaxf(m1, mx1);
        float al0 = exp2f(m0 - mn0), al1 = exp2f(m1 - mn1);
        m0 = mn0; m1 = mn1;

        float rs0 = 0.0f, rs1 = 0.0f;
#pragma unroll
        for (int j = 0; j < 8; j++) {
            sS[j][0] = exp2f(sS[j][0] - mn0);
            sS[j][1] = exp2f(sS[j][1] - mn0);
            sS[j][2] = exp2f(sS[j][2] - mn1);
            sS[j][3] = exp2f(sS[j][3] - mn1);
            rs0 += sS[j][0] + sS[j][1];
            rs1 += sS[j][2] + sS[j][3];
        }
        rs0 += __shfl_xor_sync(0xffffffffu, rs0, 1);
        rs0 += __shfl_xor_sync(0xffffffffu, rs0, 2);
        rs1 += __shfl_xor_sync(0xffffffffu, rs1, 1);
        rs1 += __shfl_xor_sync(0xffffffffu, rs1, 2);
        l0 = l0 * al0 + rs0;
        l1 = l1 * al1 + rs1;

#pragma unroll
        for (int j = 0; j < 8; j++) {
            ctx[j][0] *= al0; ctx[j][1] *= al0;
            ctx[j][2] *= al1; ctx[j][3] *= al1;
        }

        // ---- ctx += P @ V (single fp16 P) ----
        const uint32_t vAddr = st + VF_OFF + (uint32_t)(lane & 15) * AT_STRIDE + (lane >> 4) * 16;
#pragma unroll
        for (int kc = 0; kc < 4; kc++) {
            uint32_t aP[4];
            aP[0] = packh(sS[2*kc][0],   sS[2*kc][1]);
            aP[1] = packh(sS[2*kc][2],   sS[2*kc][3]);
            aP[2] = packh(sS[2*kc+1][0], sS[2*kc+1][1]);
            aP[3] = packh(sS[2*kc+1][2], sS[2*kc+1][3]);

#pragma unroll
            for (int dp = 0; dp < 4; dp++) {
                uint32_t t[4];
                ldsm4t(vAddr + kc * 2304 + dp * 32, t);
                uint32_t b0[2] = { t[0], t[1] }, b1[2] = { t[2], t[3] };
                mma_f16(ctx[2*dp],   aP, b0);
                mma_f16(ctx[2*dp+1], aP, b1);
            }
        }
        __syncthreads();
    }

    // ---- epilogue: normalize, write split fp16 ctx [b, s, hq*64+d] ----
    float inv0 = 1.0f / l0, inv1 = 1.0f / l1;
    int r0 = q0 + wid * 16 + (lane >> 2);
    size_t obase = (size_t)b * SS * DM + (size_t)hq * 64;
#pragma unroll
    for (int nj = 0; nj < 8; nj++) {
        int cc = nj * 8 + (lane & 3) * 2;
        split_store_h(Ch, Cl, obase + (size_t)r0 * DM + cc,
                      ctx[nj][0] * inv0, ctx[nj][1] * inv0);
        split_store_h(Ch, Cl, obase + (size_t)(r0 + 8) * DM + cc,
                      ctx[nj][2] * inv1, ctx[nj][3] * inv1);
    }
}

// ---------------------------------------------------------------------------
extern "C" void kernel_launch(void* const* d_in, const int* in_sizes, int n_in,
                              void* d_out, int out_size)
{
    const float* q  = (const float*)d_in[0];
    const float* k  = (const float*)d_in[1];
    const float* v  = (const float*)d_in[2];
    const float* Wq = (const float*)d_in[3];
    const float* Wk = (const float*)d_in[4];
    const float* Wv = (const float*)d_in[5];
    const float* Wo = (const float*)d_in[6];
    float* out = (float*)d_out;

    __half *WqF, *WkF, *WvF, *WoF, *Ch, *Cl, *Qf, *Kf, *Vf;
    cudaGetSymbolAddress((void**)&WqF, g_WqF);
    cudaGetSymbolAddress((void**)&WkF, g_WkF);
    cudaGetSymbolAddress((void**)&WvF, g_WvF);
    cudaGetSymbolAddress((void**)&WoF, g_WoF);
    cudaGetSymbolAddress((void**)&Ch, g_Ch);
    cudaGetSymbolAddress((void**)&Cl, g_Cl);
    cudaGetSymbolAddress((void**)&Qf, g_Qf);
    cudaGetSymbolAddress((void**)&Kf, g_Kf);
    cudaGetSymbolAddress((void**)&Vf, g_Vf);

    cudaFuncSetAttribute((const void*)&gemm_hmma<0,2,32,256>, cudaFuncAttributeMaxDynamicSharedMemorySize, GEMM_SMEM_256);
    cudaFuncSetAttribute((const void*)&gemm_hmma<0,2,8,128>,  cudaFuncAttributeMaxDynamicSharedMemorySize, GEMM_SMEM_128);
    cudaFuncSetAttribute((const void*)&gemm_hmma<1,0,0,256>,  cudaFuncAttributeMaxDynamicSharedMemorySize, GEMM_SMEM_256);
    cudaFuncSetAttribute((const void*)&attn_mma,              cudaFuncAttributeMaxDynamicSharedMemorySize, ATT_SMEM);

    dim3 wblk(32, 8);

    // weight converts: 2 fused launches (z selects weight)
    wconv2<<<dim3(DM / 32, KDIM / 32, 2), wblk>>>(Wq, WqF, Wo, WoF, DM);
    wconv2<<<dim3(DKV / 32, KDIM / 32, 2), wblk>>>(Wk, WkF, Wv, WvF, DKV);

    // Q projection: single scaled fp16 out, head-major
    gemm_hmma<0,2,32,256><<<dim3(DM / 256, ROWS / 128), 256, GEMM_SMEM_256>>>(
        q, nullptr, nullptr, WqF, nullptr, Qf, nullptr, SCALE_Q, DM,
        nullptr, nullptr, nullptr);

    // K + V projections fused into one launch (blockIdx.z)
    gemm_hmma<0,2,8,128><<<dim3(DKV / 128, ROWS / 128, 2), 256, GEMM_SMEM_128>>>(
        k, nullptr, nullptr, WkF, nullptr, Kf, nullptr, 1.0f, DKV,
        v, WvF, Vf);

    // attention (single fp16 Q/K/P/V, writes split fp16 ctx)
    attn_mma<<<dim3(SS / 128, BB * HQn), 256, ATT_SMEM>>>(Qf, Kf, Vf, Ch, Cl);

    // output projection: split fp16 A in, fp32 out
    gemm_hmma<1,0,0,256><<<dim3(DM / 256, ROWS / 128), 256, GEMM_SMEM_256>>>(
        nullptr, Ch, Cl, WoF, out, nullptr, nullptr, 1.0f, DM,
        nullptr, nullptr, nullptr);
}

// round 10
// speedup vs baseline: 1.3814x; 1.0861x over previous
#include <cuda_runtime.h>
#include <cuda_fp16.h>
#include <cstdint>
#include <math.h>

#define BB   2
#define SS   2048
#define DM   2048
#define HQn  32
#define HKVn 8
#define DHn  64
#define ROWS (BB * SS)          // 4096
#define DKV  (HKVn * DHn)       // 512
#define KDIM 2048

#define SCALE_Q (0.125f * 1.44269504088896340736f)   // 1/sqrt(64) * log2(e)

// ---------------- scratch ----------------
__device__ __half g_WqF[DM * DM];                 // transposed fp16 weights [N][K]
__device__ __half g_WkF[DKV * KDIM];
__device__ __half g_WvF[DKV * KDIM];
__device__ __half g_WoF[DM * DM];
__device__ __half g_Ch[ROWS * DM];                // split attention ctx hi
__device__ __half g_Cl[ROWS * DM];                // split attention ctx lo
__device__ __half g_Qf[BB * HQn * SS * DHn];      // [b,hq,s,d] single fp16 (pre-scaled)
__device__ __half g_Kf[BB * HKVn * SS * DHn];     // [b,hk,s,d] single fp16
__device__ __half g_Vf[BB * HKVn * SS * DHn];

// ---------------- helpers ----------------
__device__ __forceinline__ uint32_t smem_u32(const void* p) {
    uint32_t r;
    asm("{ .reg .u64 t; cvta.to.shared.u64 t, %1; cvt.u32.u64 %0, t; }" : "=r"(r) : "l"(p));
    return r;
}
__device__ __forceinline__ uint32_t packh(float x0, float x1) {
    uint32_t r;   // mem order: low half = x0
    asm("cvt.rn.f16x2.f32 %0, %1, %2;" : "=r"(r) : "f"(x1), "f"(x0));
    return r;
}
__device__ __forceinline__ void sts64(uint32_t a, uint32_t x, uint32_t y) {
    asm volatile("st.shared.v2.b32 [%0], {%1,%2};" :: "r"(a), "r"(x), "r"(y));
}
__device__ __forceinline__ void sts128(uint32_t a, uint4 v) {
    asm volatile("st.shared.v4.b32 [%0], {%1,%2,%3,%4};"
                 :: "r"(a), "r"(v.x), "r"(v.y), "r"(v.z), "r"(v.w));
}
__device__ __forceinline__ void ldsm4(uint32_t a, uint32_t r[4]) {
    asm volatile("ldmatrix.sync.aligned.m8n8.x4.shared.b16 {%0,%1,%2,%3}, [%4];"
                 : "=r"(r[0]), "=r"(r[1]), "=r"(r[2]), "=r"(r[3]) : "r"(a));
}
__device__ __forceinline__ void ldsm4t(uint32_t a, uint32_t r[4]) {
    asm volatile("ldmatrix.sync.aligned.m8n8.x4.trans.shared.b16 {%0,%1,%2,%3}, [%4];"
                 : "=r"(r[0]), "=r"(r[1]), "=r"(r[2]), "=r"(r[3]) : "r"(a));
}
__device__ __forceinline__ void mma_f16(float c[4], const uint32_t a[4], const uint32_t b[2]) {
    asm volatile("mma.sync.aligned.m16n8k16.row.col.f32.f16.f16.f32 "
                 "{%0,%1,%2,%3},{%4,%5,%6,%7},{%8,%9},{%0,%1,%2,%3};"
                 : "+f"(c[0]), "+f"(c[1]), "+f"(c[2]), "+f"(c[3])
                 : "r"(a[0]), "r"(a[1]), "r"(a[2]), "r"(a[3]), "r"(b[0]), "r"(b[1]));
}
__device__ __forceinline__ void cp16(uint32_t dst, const void* src) {
    asm volatile("cp.async.cg.shared.global [%0], [%1], 16;" :: "r"(dst), "l"(src));
}
#define CP_COMMIT() asm volatile("cp.async.commit_group;" ::: "memory")
template<int N> __device__ __forceinline__ void cp_wait() {
    asm volatile("cp.async.wait_group %0;" :: "n"(N) : "memory");
}
__device__ __forceinline__ void split_store_h(__half* Ch, __half* Cl,
                                              size_t idx, float x0, float x1) {
    float h0 = __half2float(__float2half(x0));
    float h1 = __half2float(__float2half(x1));
    *(uint32_t*)(Ch + idx) = packh(x0, x1);
    *(uint32_t*)(Cl + idx) = packh(x0 - h0, x1 - h1);
}

// ---------------------------------------------------------------------------
// Weight transpose + fp16 round, two weights per launch (blockIdx.z selects):
// Wf[n][k] = (half) W[k][n]
// ---------------------------------------------------------------------------
__global__ __launch_bounds__(256)
void wconv2(const float* __restrict__ W0, __half* __restrict__ F0,
            const float* __restrict__ W1, __half* __restrict__ F1, int N)
{
    const float* W = blockIdx.z ? W1 : W0;
    __half* Wf = blockIdx.z ? F1 : F0;
    __shared__ float t[32][33];
    int n0 = blockIdx.x * 32, k0 = blockIdx.y * 32;
    int tx = threadIdx.x, ty = threadIdx.y;   // 32 x 8
#pragma unroll
    for (int i = ty; i < 32; i += 8)
        t[i][tx] = W[(size_t)(k0 + i) * N + n0 + tx];
    __syncthreads();
#pragma unroll
    for (int i = ty; i < 32; i += 8)
        Wf[(size_t)(n0 + i) * KDIM + k0 + tx] = __float2half(t[tx][i]);
}

// ---------------------------------------------------------------------------
// HMMA GEMM, CTA tile 128xBN, warp tile 64x(BN/4), 8 warps 2x4, BK=32,
// double-buffered smem.
// ASPLIT 1: A = Ah + Al 2-term split.  0: single fp16 A (rounded).
// blockIdx.z==1 switches to secondary (Af2, Bf2, Ch2) problem (KV fusion).
// AIN  0: A fp32 inline-converted.  1: A pre-split fp16 pair (requires ASPLIT=1).
// OUTK 0: fp32 C row-major.
//      2: single fp16 scaled, head-major [b, head, s, d] (NH heads of 64).
// ---------------------------------------------------------------------------
#define AH_OFF  0

template<int AIN, int ASPLIT, int OUTK, int NH, int BN>
__global__ __launch_bounds__(256, 1)
void gemm_hmma(const float* __restrict__ Af,
               const __half* __restrict__ Ahg, const __half* __restrict__ Alg,
               const __half* __restrict__ Bf, float* __restrict__ C,
               __half* __restrict__ Ch, __half* __restrict__ Cl,
               float scale, int N,
               const float* __restrict__ Af2, const __half* __restrict__ Bf2,
               __half* __restrict__ Ch2)
{
    constexpr int WN  = BN / 4;
    constexpr int NJ  = WN / 8;
    constexpr int NB  = WN / 16;
    constexpr int BP  = BN / 64;
    constexpr int AL_OFF = 10240;                       // only used if ASPLIT
    constexpr int B_OFF  = ASPLIT ? 20480 : 10240;
    constexpr int ST  = B_OFF + BN * 80;

    const float* AfP = (blockIdx.z ? Af2 : Af);
    const __half* BfP = (blockIdx.z ? Bf2 : Bf);
    __half* ChP = (blockIdx.z ? Ch2 : Ch);

    extern __shared__ char smem[];
    const uint32_t sb = smem_u32(smem);
    const int tid = threadIdx.x;
    const int wid = tid >> 5, lane = tid & 31;
    const int wm = wid >> 2, wn = wid & 3;
    const int m0 = blockIdx.y * 128, n0 = blockIdx.x * BN;

    const int arow = tid >> 3, acol = (tid & 7) * 4;
    const int hrow = tid >> 2, hcol = (tid & 3) * 8;

    const float* Afb = AfP + (size_t)(m0 + arow) * KDIM + acol;
    const __half* Ahb = Ahg + (size_t)(m0 + hrow) * KDIM + hcol;
    const __half* Alb = Alg + (size_t)(m0 + hrow) * KDIM + hcol;
    const __half* Bfb = BfP + (size_t)(n0 + hrow) * KDIM + hcol;

    const uint32_t aRow = (uint32_t)(wm * 64 + (lane & 15)) * 80 + (lane >> 4) * 16;
    const uint32_t bRow = (uint32_t)(wn * WN + (lane & 7) + (lane >> 4) * 8) * 80
                        + ((lane >> 3) & 1) * 16;

    float acc[4][NJ][4];
#pragma unroll
    for (int i = 0; i < 4; i++)
#pragma unroll
        for (int j = 0; j < NJ; j++)
#pragma unroll
            for (int r = 0; r < 4; r++) acc[i][j][r] = 0.0f;

    float4 fa[4];
    uint4  fah[2], fal[2], fb[BP];

    auto fetch = [&](int kc) {
        if (AIN == 0) {
#pragma unroll
            for (int p = 0; p < 4; p++)
                fa[p] = *(const float4*)(Afb + (size_t)(p * 32) * KDIM + kc);
        } else {
#pragma unroll
            for (int p = 0; p < 2; p++) {
                fah[p] = *(const uint4*)(Ahb + (size_t)(p * 64) * KDIM + kc);
                fal[p] = *(const uint4*)(Alb + (size_t)(p * 64) * KDIM + kc);
            }
        }
#pragma unroll
        for (int p = 0; p < BP; p++)
            fb[p] = *(const uint4*)(Bfb + (size_t)(p * 64) * KDIM + kc);
    };

    auto store_stage = [&](uint32_t st) {
        if (AIN == 0) {
#pragma unroll
            for (int p = 0; p < 4; p++) {
                uint32_t ad = st + (uint32_t)(arow + p * 32) * 80 + acol * 2;
                float x0 = fa[p].x, x1 = fa[p].y, x2 = fa[p].z, x3 = fa[p].w;
                sts64(ad + AH_OFF, packh(x0, x1), packh(x2, x3));
                if (ASPLIT) {
                    float h0 = __half2float(__float2half(x0));
                    float h1 = __half2float(__float2half(x1));
                    float h2 = __half2float(__float2half(x2));
                    float h3 = __half2float(__float2half(x3));
                    sts64(ad + AL_OFF, packh(x0 - h0, x1 - h1), packh(x2 - h2, x3 - h3));
                }
            }
        } else {
#pragma unroll
            for (int p = 0; p < 2; p++) {
                uint32_t ad = st + (uint32_t)(hrow + p * 64) * 80 + hcol * 2;
                sts128(ad + AH_OFF, fah[p]);
                sts128(ad + AL_OFF, fal[p]);
            }
        }
#pragma unroll
        for (int p = 0; p < BP; p++) {
            uint32_t bd = st + (uint32_t)(hrow + p * 64) * 80 + hcol * 2;
            sts128(bd + B_OFF, fb[p]);
        }
    };

    fetch(0);
    store_stage(sb);
    __syncthreads();

    const int NIT = KDIM / 32;
    for (int c = 0; c < NIT; c++) {
        const uint32_t st = sb + (uint32_t)(c & 1) * ST;

        if (c + 1 < NIT) fetch((c + 1) * 32);

#pragma unroll
        for (int ks = 0; ks < 2; ks++) {
            const uint32_t ko = ks * 32;
            uint32_t a4[4][4], bfr[NJ][2], tmpv[4];
#pragma unroll
            for (int j = 0; j < NB; j++) {
                ldsm4(st + B_OFF + bRow + j * 1280 + ko, tmpv);
                bfr[2*j][0] = tmpv[0]; bfr[2*j][1] = tmpv[1];
                bfr[2*j+1][0] = tmpv[2]; bfr[2*j+1][1] = tmpv[3];
            }
#pragma unroll
            for (int mi = 0; mi < 4; mi++)
                ldsm4(st + AH_OFF + aRow + mi * 1280 + ko, a4[mi]);
#pragma unroll
            for (int mi = 0; mi < 4; mi++)
#pragma unroll
                for (int nj = 0; nj < NJ; nj++)
                    mma_f16(acc[mi][nj], a4[mi], bfr[nj]);
            if (ASPLIT) {
#pragma unroll
                for (int mi = 0; mi < 4; mi++)
                    ldsm4(st + AL_OFF + aRow + mi * 1280 + ko, a4[mi]);
#pragma unroll
                for (int mi = 0; mi < 4; mi++)
#pragma unroll
                    for (int nj = 0; nj < NJ; nj++)
                        mma_f16(acc[mi][nj], a4[mi], bfr[nj]);
            }
        }

        if (c + 1 < NIT) store_stage(sb + (uint32_t)((c + 1) & 1) * ST);
        __syncthreads();
    }

    const int rbase = m0 + wm * 64 + (lane >> 2);
    const int cbase = n0 + wn * WN + (lane & 3) * 2;
#pragma unroll
    for (int mi = 0; mi < 4; mi++)
#pragma unroll
        for (int nj = 0; nj < NJ; nj++) {
            int r0 = rbase + mi * 16;
            int cc = cbase + nj * 8;
            if (OUTK == 0) {
                *(float2*)(C + (size_t)r0 * N + cc)       = make_float2(acc[mi][nj][0], acc[mi][nj][1]);
                *(float2*)(C + (size_t)(r0 + 8) * N + cc) = make_float2(acc[mi][nj][2], acc[mi][nj][3]);
            } else {
                int bb0 = r0 >> 11, ss0 = r0 & 2047;
                int hh = cc >> 6, dd = cc & 63;
                size_t i0 = (((size_t)(bb0 * NH + hh)) * SS + ss0) * 64 + dd;
                int r1 = r0 + 8;
                int bb1 = r1 >> 11, ss1 = r1 & 2047;
                size_t i1 = (((size_t)(bb1 * NH + hh)) * SS + ss1) * 64 + dd;
                *(uint32_t*)(ChP + i0) = packh(acc[mi][nj][0] * scale, acc[mi][nj][1] * scale);
                *(uint32_t*)(ChP + i1) = packh(acc[mi][nj][2] * scale, acc[mi][nj][3] * scale);
            }
        }
}

#define GEMM_SMEM_Q  (2 * (10240 + 256 * 80))   // 61440  (ASPLIT=0, BN=256)
#define GEMM_SMEM_KV (2 * (10240 + 128 * 80))   // 40960  (ASPLIT=0, BN=128)
#define GEMM_SMEM_O  (2 * (20480 + 256 * 80))   // 81920  (ASPLIT=1, BN=256)

// ---------------------------------------------------------------------------
// HMMA flash attention, single-fp16 QK and PV. 2 CTAs/SM.
// ---------------------------------------------------------------------------
#define AT_STRIDE 144
#define KF_OFF 0
#define VF_OFF 9216
#define AT_STAGE 18432
#define ATT_SMEM (2 * AT_STAGE)   // 36864

__global__ __launch_bounds__(256, 2)
void attn_mma(const __half* __restrict__ Qf_, const __half* __restrict__ Kf_,
              const __half* __restrict__ Vf_,
              __half* __restrict__ Ch, __half* __restrict__ Cl)
{
    extern __shared__ char smem[];
    const uint32_t sb = smem_u32(smem);
    const int tid = threadIdx.x, wid = tid >> 5, lane = tid & 31;
    const int bh = blockIdx.y;
    const int b = bh >> 5, hq = bh & 31, hk = hq >> 2;
    const int q0 = blockIdx.x * 128;

    const __half* Qfb = Qf_ + ((size_t)bh * SS + q0) * 64;
    const size_t kvoff = (size_t)(b * HKVn + hk) * SS * 64;
    const __half* Kfb = Kf_ + kvoff;
    const __half* Vfb = Vf_ + kvoff;

    for (int i = tid; i < 1024; i += 256) {
        int r = i >> 3, ch = i & 7;
        *(uint4*)(smem + r * AT_STRIDE + ch * 16) = *(const uint4*)(Qfb + (size_t)r * 64 + ch * 8);
    }
    __syncthreads();

    uint32_t qh[4][4];
    {
        uint32_t aAddr = sb + (uint32_t)(wid * 16 + (lane & 15)) * AT_STRIDE + (lane >> 4) * 16;
#pragma unroll
        for (int kc = 0; kc < 4; kc++)
            ldsm4(aAddr + kc * 32, qh[kc]);
    }
    __syncthreads();

    auto load_tile = [&](int kt, uint32_t st) {
        size_t base = (size_t)kt * 64 * 64;
#pragma unroll
        for (int i = tid; i < 512; i += 256) {
            int r = i >> 3, ch = i & 7;
            uint32_t d = st + r * AT_STRIDE + ch * 16;
            size_t s = base + (size_t)r * 64 + ch * 8;
            cp16(d + KF_OFF, Kfb + s);
            cp16(d + VF_OFF, Vfb + s);
        }
    };

    float m0 = -1e30f, m1 = -1e30f, l0 = 0.0f, l1 = 0.0f;
    float ctx[8][4];
#pragma unroll
    for (int j = 0; j < 8; j++)
#pragma unroll
        for (int e = 0; e < 4; e++) ctx[j][e] = 0.0f;

    load_tile(0, sb);
    CP_COMMIT();

    const int NKT = SS / 64;
    for (int kt = 0; kt < NKT; kt++) {
        const uint32_t st = sb + (uint32_t)(kt & 1) * AT_STAGE;
        if (kt + 1 < NKT) {
            load_tile(kt + 1, sb + (uint32_t)((kt + 1) & 1) * AT_STAGE);
            CP_COMMIT();
            cp_wait<1>();
        } else {
            cp_wait<0>();
        }
        __syncthreads();

        float sS[8][4];
#pragma unroll
        for (int j = 0; j < 8; j++)
#pragma unroll
            for (int e = 0; e < 4; e++) sS[j][e] = 0.0f;

        const uint32_t kAddr = st + KF_OFF + (uint32_t)((lane >> 4) * 8 + (lane & 7)) * AT_STRIDE
                             + ((lane >> 3) & 1) * 16;
#pragma unroll
        for (int kc = 0; kc < 4; kc++) {
            uint32_t bK[8][2], t[4];
#pragma unroll
            for (int np = 0; np < 4; np++) {
                ldsm4(kAddr + np * 2304 + kc * 32, t);
                bK[2*np][0] = t[0]; bK[2*np][1] = t[1];
                bK[2*np+1][0] = t[2]; bK[2*np+1][1] = t[3];
            }
#pragma unroll
            for (int nj = 0; nj < 8; nj++) mma_f16(sS[nj], qh[kc], bK[nj]);
        }

        float mx0 = -1e30f, mx1 = -1e30f;
#pragma unroll
        for (int j = 0; j < 8; j++) {
            mx0 = fmaxf(mx0, fmaxf(sS[j][0], sS[j][1]));
            mx1 = fmaxf(mx1, fmaxf(sS[j][2], sS[j][3]));
        }
        mx0 = fmaxf(mx0, __shfl_xor_sync(0xffffffffu, mx0, 1));
        mx0 = fmaxf(mx0, __shfl_xor_sync(0xffffffffu, mx0, 2));
        mx1 = fmaxf(mx1, __shfl_xor_sync(0xffffffffu, mx1, 1));
        mx1 = fmaxf(mx1, __shfl_xor_sync(0xffffffffu, mx1, 2));

        float mn0 = fmaxf(m0, mx0), mn1 = fmaxf(m1, mx1);
        float al0 = exp2f(m0 - mn0), al1 = exp2f(m1 - mn1);
        m0 = mn0; m1 = mn1;

        float rs0 = 0.0f, rs1 = 0.0f;
#pragma unroll
        for (int j = 0; j < 8; j++) {
            sS[j][0] = exp2f(sS[j][0] - mn0);
            sS[j][1] = exp2f(sS[j][1] - mn0);
            sS[j][2] = exp2f(sS[j][2] - mn1);
            sS[j][3] = exp2f(sS[j][3] - mn1);
            rs0 += sS[j][0] + sS[j][1];
            rs1 += sS[j][2] + sS[j][3];
        }
        rs0 += __shfl_xor_sync(0xffffffffu, rs0, 1);
        rs0 += __shfl_xor_sync(0xffffffffu, rs0, 2);
        rs1 += __shfl_xor_sync(0xffffffffu, rs1, 1);
        rs1 += __shfl_xor_sync(0xffffffffu, rs1, 2);
        l0 = l0 * al0 + rs0;
        l1 = l1 * al1 + rs1;

#pragma unroll
        for (int j = 0; j < 8; j++) {
            ctx[j][0] *= al0; ctx[j][1] *= al0;
            ctx[j][2] *= al1; ctx[j][3] *= al1;
        }

        const uint32_t vAddr = st + VF_OFF + (uint32_t)(lane & 15) * AT_STRIDE + (lane >> 4) * 16;
#pragma unroll
        for (int kc = 0; kc < 4; kc++) {
            uint32_t aP[4];
            aP[0] = packh(sS[2*kc][0],   sS[2*kc][1]);
            aP[1] = packh(sS[2*kc][2],   sS[2*kc][3]);
            aP[2] = packh(sS[2*kc+1][0], sS[2*kc+1][1]);
            aP[3] = packh(sS[2*kc+1][2], sS[2*kc+1][3]);

#pragma unroll
            for (int dp = 0; dp < 4; dp++) {
                uint32_t t[4];
                ldsm4t(vAddr + kc * 2304 + dp * 32, t);
                uint32_t b0[2] = { t[0], t[1] }, b1[2] = { t[2], t[3] };
                mma_f16(ctx[2*dp],   aP, b0);
                mma_f16(ctx[2*dp+1], aP, b1);
            }
        }
        __syncthreads();
    }

    float inv0 = 1.0f / l0, inv1 = 1.0f / l1;
    int r0 = q0 + wid * 16 + (lane >> 2);
    size_t obase = (size_t)b * SS * DM + (size_t)hq * 64;
#pragma unroll
    for (int nj = 0; nj < 8; nj++) {
        int cc = nj * 8 + (lane & 3) * 2;
        split_store_h(Ch, Cl, obase + (size_t)r0 * DM + cc,
                      ctx[nj][0] * inv0, ctx[nj][1] * inv0);
        split_store_h(Ch, Cl, obase + (size_t)(r0 + 8) * DM + cc,
                      ctx[nj][2] * inv1, ctx[nj][3] * inv1);
    }
}

// ---------------------------------------------------------------------------
extern "C" void kernel_launch(void* const* d_in, const int* in_sizes, int n_in,
                              void* d_out, int out_size)
{
    const float* q  = (const float*)d_in[0];
    const float* k  = (const float*)d_in[1];
    const float* v  = (const float*)d_in[2];
    const float* Wq = (const float*)d_in[3];
    const float* Wk = (const float*)d_in[4];
    const float* Wv = (const float*)d_in[5];
    const float* Wo = (const float*)d_in[6];
    float* out = (float*)d_out;

    __half *WqF, *WkF, *WvF, *WoF, *Ch, *Cl, *Qf, *Kf, *Vf;
    cudaGetSymbolAddress((void**)&WqF, g_WqF);
    cudaGetSymbolAddress((void**)&WkF, g_WkF);
    cudaGetSymbolAddress((void**)&WvF, g_WvF);
    cudaGetSymbolAddress((void**)&WoF, g_WoF);
    cudaGetSymbolAddress((void**)&Ch, g_Ch);
    cudaGetSymbolAddress((void**)&Cl, g_Cl);
    cudaGetSymbolAddress((void**)&Qf, g_Qf);
    cudaGetSymbolAddress((void**)&Kf, g_Kf);
    cudaGetSymbolAddress((void**)&Vf, g_Vf);

    cudaFuncSetAttribute((const void*)&gemm_hmma<0,0,2,32,256>, cudaFuncAttributeMaxDynamicSharedMemorySize, GEMM_SMEM_Q);
    cudaFuncSetAttribute((const void*)&gemm_hmma<0,0,2,8,128>,  cudaFuncAttributeMaxDynamicSharedMemorySize, GEMM_SMEM_KV);
    cudaFuncSetAttribute((const void*)&gemm_hmma<1,1,0,0,256>,  cudaFuncAttributeMaxDynamicSharedMemorySize, GEMM_SMEM_O);
    cudaFuncSetAttribute((const void*)&attn_mma,                cudaFuncAttributeMaxDynamicSharedMemorySize, ATT_SMEM);

    dim3 wblk(32, 8);

    // weight converts: 2 fused launches (z selects weight)
    wconv2<<<dim3(DM / 32, KDIM / 32, 2), wblk>>>(Wq, WqF, Wo, WoF, DM);
    wconv2<<<dim3(DKV / 32, KDIM / 32, 2), wblk>>>(Wk, WkF, Wv, WvF, DKV);

    // Q projection: single fp16 A (no split), single scaled fp16 out
    gemm_hmma<0,0,2,32,256><<<dim3(DM / 256, ROWS / 128), 256, GEMM_SMEM_Q>>>(
        q, nullptr, nullptr, WqF, nullptr, Qf, nullptr, SCALE_Q, DM,
        nullptr, nullptr, nullptr);

    // K + V projections fused (blockIdx.z), single fp16 A
    gemm_hmma<0,0,2,8,128><<<dim3(DKV / 128, ROWS / 128, 2), 256, GEMM_SMEM_KV>>>(
        k, nullptr, nullptr, WkF, nullptr, Kf, nullptr, 1.0f, DKV,
        v, WvF, Vf);

    // attention (single fp16 Q/K/P/V, writes split fp16 ctx)
    attn_mma<<<dim3(SS / 128, BB * HQn), 256, ATT_SMEM>>>(Qf, Kf, Vf, Ch, Cl);

    // output projection: split fp16 A (ctx hi/lo), fp32 out
    gemm_hmma<1,1,0,0,256><<<dim3(DM / 256, ROWS / 128), 256, GEMM_SMEM_O>>>(
        nullptr, Ch, Cl, WoF, out, nullptr, nullptr, 1.0f, DM,
        nullptr, nullptr, nullptr);
}